// round 14
// baseline (speedup 1.0000x reference)
#include <cuda_runtime.h>
#include <cuda_fp16.h>
#include <math.h>

#define B_  2
#define L_  1024
#define H_  16
#define D_  64
#define HID_ 1024
#define N3_ 3072
#define HD_ 1024   // H*D
#define M_  2048   // B*L

// ---------------- scratch (device globals; no allocations) ----------------
__device__ float g_q[B_ * H_ * L_ * D_];   // fp32 post-QKV (pre-RoPE)
__device__ float g_k[B_ * H_ * L_ * D_];
__device__ float g_v[B_ * H_ * L_ * D_];
__device__ unsigned g_qh[B_ * H_ * L_ * (D_ / 2)];  // RoPE'd q, half2 packed along d
__device__ unsigned g_kh[B_ * H_ * L_ * (D_ / 2)];
__device__ float g_s[B_ * H_ * L_ * L_];   // raw scores, 128 MB
__device__ __half g_w[B_ * H_ * L_ * L_];  // softmax weights fp16 (zero-init above diag)
__device__ unsigned g_vtp[B_ * H_ * D_ * (L_ / 2)];  // V transposed, half2 packed along l
__device__ unsigned g_oh[M_ * (HD_ / 2)];  // attention out, half2 packed
__device__ float g_kt[L_ * H_];            // kerple table [dist][h]
__device__ unsigned g_xh[M_ * (HID_ / 2)];           // packed x
__device__ unsigned g_wqkvh[(HID_ / 2) * N3_];       // packed w_qkv [kp][n]
__device__ unsigned g_woh[(HID_ / 2) * HID_];        // packed w_o   [kp][n]

// ---------------- helpers ----------------
__device__ __forceinline__ unsigned pk_bf16(float lo, float hi) {
    unsigned r;
    asm("cvt.rn.bf16x2.f32 %0, %1, %2;" : "=r"(r) : "f"(hi), "f"(lo));
    return r;
}

__device__ __forceinline__ unsigned pk_h(float lo, float hi) {
    unsigned r;
    asm("cvt.rn.f16x2.f32 %0, %1, %2;" : "=r"(r) : "f"(hi), "f"(lo));
    return r;
}

__device__ __forceinline__ void mma_bf16(float& d0, float& d1, float& d2, float& d3,
                                         unsigned a0, unsigned a1, unsigned a2, unsigned a3,
                                         unsigned b0, unsigned b1) {
    asm volatile(
        "mma.sync.aligned.m16n8k16.row.col.f32.bf16.bf16.f32 "
        "{%0,%1,%2,%3}, {%4,%5,%6,%7}, {%8,%9}, {%0,%1,%2,%3};"
        : "+f"(d0), "+f"(d1), "+f"(d2), "+f"(d3)
        : "r"(a0), "r"(a1), "r"(a2), "r"(a3), "r"(b0), "r"(b1));
}

__device__ __forceinline__ void mma_f16(float& d0, float& d1, float& d2, float& d3,
                                        unsigned a0, unsigned a1, unsigned a2, unsigned a3,
                                        unsigned b0, unsigned b1) {
    asm volatile(
        "mma.sync.aligned.m16n8k16.row.col.f32.f16.f16.f32 "
        "{%0,%1,%2,%3}, {%4,%5,%6,%7}, {%8,%9}, {%0,%1,%2,%3};"
        : "+f"(d0), "+f"(d1), "+f"(d2), "+f"(d3)
        : "r"(a0), "r"(a1), "r"(a2), "r"(a3), "r"(b0), "r"(b1));
}

// ---------------- pack kernels ----------------
__global__ void k_packA(const float* __restrict__ in, unsigned* __restrict__ out) {
    int t = blockIdx.x * 256 + threadIdx.x;
    float2 v = reinterpret_cast<const float2*>(in)[t];
    out[t] = pk_h(v.x, v.y);
}

template<int N>
__global__ void k_packB(const float* __restrict__ in, unsigned* __restrict__ out) {
    int t = blockIdx.x * 256 + threadIdx.x;
    int kp = t / N, n = t - kp * N;
    out[t] = pk_h(in[(size_t)(2 * kp) * N + n], in[(size_t)(2 * kp + 1) * N + n]);
}

// ---------------- packed fp16 GEMM, 128 threads, BM=64 BN=64 BK=32 ----------------
// A packed [row][kp] (512 uints/row); B packed [kp][n]. High-occupancy small tiles.
template<int NLD, int MODE>
__global__ void __launch_bounds__(128)
k_gemm_hp(const unsigned* __restrict__ A, const unsigned* __restrict__ Bm, float* __restrict__ C) {
    __shared__ unsigned sAp[64 * 20];
    __shared__ unsigned sBp[16 * 68];

    int tid = threadIdx.x;
    int lane = tid & 31, wid = tid >> 5;
    int g = lane >> 2, t4 = lane & 3;
    int wm = wid & 1, wn = wid >> 1;
    int m0 = blockIdx.y * 64, n0 = blockIdx.x * 64;

    float acc[2][4][4];
    #pragma unroll
    for (int mt = 0; mt < 2; mt++)
        #pragma unroll
        for (int nt = 0; nt < 4; nt++)
            #pragma unroll
            for (int c = 0; c < 4; c++) acc[mt][nt][c] = 0.0f;

    uint4 ra[2], rb[2];
    #pragma unroll
    for (int u = 0; u < 2; u++) {
        int id = u * 128 + tid;
        int row = id >> 2, seg = (id & 3) * 4;
        ra[u] = *reinterpret_cast<const uint4*>(A + (size_t)(m0 + row) * 512 + seg);
        int kp = id >> 4, n4 = (id & 15) * 4;
        rb[u] = *reinterpret_cast<const uint4*>(Bm + (size_t)kp * NLD + n0 + n4);
    }

    for (int k0p = 0; k0p < 512; k0p += 16) {
        #pragma unroll
        for (int u = 0; u < 2; u++) {
            int id = u * 128 + tid;
            int row = id >> 2, seg = (id & 3) * 4;
            sAp[row * 20 + seg + 0] = ra[u].x;
            sAp[row * 20 + seg + 1] = ra[u].y;
            sAp[row * 20 + seg + 2] = ra[u].z;
            sAp[row * 20 + seg + 3] = ra[u].w;
            int kp = id >> 4, n4 = (id & 15) * 4;
            sBp[kp * 68 + n4 + 0] = rb[u].x;
            sBp[kp * 68 + n4 + 1] = rb[u].y;
            sBp[kp * 68 + n4 + 2] = rb[u].z;
            sBp[kp * 68 + n4 + 3] = rb[u].w;
        }
        __syncthreads();

        if (k0p + 16 < 512) {
            #pragma unroll
            for (int u = 0; u < 2; u++) {
                int id = u * 128 + tid;
                int row = id >> 2, seg = (id & 3) * 4;
                ra[u] = *reinterpret_cast<const uint4*>(A + (size_t)(m0 + row) * 512 + k0p + 16 + seg);
                int kp = id >> 4, n4 = (id & 15) * 4;
                rb[u] = *reinterpret_cast<const uint4*>(Bm + (size_t)(k0p + 16 + kp) * NLD + n0 + n4);
            }
        }

        #pragma unroll
        for (int s = 0; s < 2; s++) {
            int kb = s * 8;
            unsigned af[2][4];
            #pragma unroll
            for (int mt = 0; mt < 2; mt++) {
                int r = wm * 32 + mt * 16 + g;
                af[mt][0] = sAp[r * 20 + kb + t4];
                af[mt][1] = sAp[(r + 8) * 20 + kb + t4];
                af[mt][2] = sAp[r * 20 + kb + t4 + 4];
                af[mt][3] = sAp[(r + 8) * 20 + kb + t4 + 4];
            }
            #pragma unroll
            for (int nt = 0; nt < 4; nt++) {
                int n = wn * 32 + nt * 8 + g;
                unsigned b0 = sBp[(kb + t4) * 68 + n];
                unsigned b1 = sBp[(kb + t4 + 4) * 68 + n];
                #pragma unroll
                for (int mt = 0; mt < 2; mt++)
                    mma_f16(acc[mt][nt][0], acc[mt][nt][1], acc[mt][nt][2], acc[mt][nt][3],
                            af[mt][0], af[mt][1], af[mt][2], af[mt][3], b0, b1);
            }
        }
        __syncthreads();
    }

    #pragma unroll
    for (int mt = 0; mt < 2; mt++) {
        #pragma unroll
        for (int nt = 0; nt < 4; nt++) {
            int row = m0 + wm * 32 + mt * 16 + g;
            int col = n0 + wn * 32 + nt * 8 + t4 * 2;
            if (MODE == 0) {
                *reinterpret_cast<float2*>(C + (size_t)row * NLD + col) =
                    make_float2(acc[mt][nt][0], acc[mt][nt][1]);
                *reinterpret_cast<float2*>(C + (size_t)(row + 8) * NLD + col) =
                    make_float2(acc[mt][nt][2], acc[mt][nt][3]);
            } else {
                #pragma unroll
                for (int half = 0; half < 2; half++) {
                    int m = row + half * 8;
                    int b = m >> 10, l = m & 1023;
                    int s = col >> 10, rem = col & 1023;
                    int h = rem >> 6, d = rem & 63;
                    float* dst = (s == 0) ? g_q : (s == 1) ? g_k : g_v;
                    *reinterpret_cast<float2*>(dst + (size_t)((b * H_ + h) * L_ + l) * D_ + d) =
                        make_float2(acc[mt][nt][half * 2], acc[mt][nt][half * 2 + 1]);
                }
            }
        }
    }
}

// ---------------- kernel 2: RoPE -> packed fp16 q/k ----------------
__global__ void k_rope2() {
    int t = blockIdx.x * 256 + threadIdx.x;
    int bh = t >> 15;
    int rem = t & 32767;
    int l = rem >> 5;
    int j = rem & 31;
    float invf = expf(-(float)j * (logf(10000.0f) / 32.0f));
    float ang = (float)l * invf;
    float cs = cosf(ang), sn = sinf(ang);
    int base = (bh << 16) + (l << 6) + j;
    float q1 = g_q[base], q2 = g_q[base + 32];
    float qa = q1 * cs - q2 * sn;
    float qb = q2 * cs + q1 * sn;
    float k1 = g_k[base], k2 = g_k[base + 32];
    float ka = k1 * cs - k2 * sn;
    float kb = k2 * cs + k1 * sn;

    float qan = __shfl_down_sync(0xffffffffu, qa, 1);
    float qbn = __shfl_down_sync(0xffffffffu, qb, 1);
    float kan = __shfl_down_sync(0xffffffffu, ka, 1);
    float kbn = __shfl_down_sync(0xffffffffu, kb, 1);
    if ((j & 1) == 0) {
        int rowo = (bh << 10) + l;
        int p = j >> 1;
        g_qh[rowo * 32 + p]      = pk_h(qa, qan);
        g_qh[rowo * 32 + 16 + p] = pk_h(qb, qbn);
        g_kh[rowo * 32 + p]      = pk_h(ka, kan);
        g_kh[rowo * 32 + 16 + p] = pk_h(kb, kbn);
    }
}

// ---------------- kernel 2b: kerple table [dist][h] ----------------
__global__ void k_ktab(const float* __restrict__ log_p, const float* __restrict__ log_a) {
    int d = blockIdx.x * 256 + threadIdx.x;
    if (d >= L_) return;
    float dist = (float)d;
    #pragma unroll
    for (int h = 0; h < H_; h++) {
        float p = log1pf(expf(log_p[h]));
        float a = log1pf(expf(log_a[h]));
        g_kt[d * H_ + h] = -p * log1pf(a * dist);
    }
}

// ---------------- kernel 2c: transpose V -> g_vtp[bh][d][l/2] half2 ----------------
__global__ void __launch_bounds__(256) k_vt() {
    int lb = blockIdx.x;
    int bh = blockIdx.y;
    __shared__ float sT[128][65];
    int tid = threadIdx.x;
    const float* vb = g_v + ((size_t)bh * L_ + lb * 128) * D_;
    #pragma unroll
    for (int u = 0; u < 8; u++) {
        int id = u * 256 + tid;
        int l = id >> 4, c4 = (id & 15) * 4;
        float4 v = *reinterpret_cast<const float4*>(vb + l * D_ + c4);
        sT[l][c4] = v.x; sT[l][c4 + 1] = v.y; sT[l][c4 + 2] = v.z; sT[l][c4 + 3] = v.w;
    }
    __syncthreads();
    unsigned* out = g_vtp + (size_t)bh * D_ * (L_ / 2) + lb * 64;
    #pragma unroll
    for (int u = 0; u < 16; u++) {
        int id = u * 256 + tid;
        int d = id >> 6, lp = id & 63;
        out[(size_t)d * (L_ / 2) + lp] = pk_h(sT[2 * lp][d], sT[2 * lp + 1][d]);
    }
}

// ---------------- kernel 3: scores = q k^T * scale (fp16 mma, 128x128, single-shot D) ----------------
__global__ void __launch_bounds__(256) k_scores_h() {
    int jt = blockIdx.x, it = blockIdx.y, bh = blockIdx.z;
    if (jt > it) return;
    int i0 = it * 128, j0 = jt * 128;
    __shared__ unsigned sQp[128 * 33];
    __shared__ unsigned sKp[128 * 33];

    int tid = threadIdx.x;
    int lane = tid & 31, wid = tid >> 5;
    int g = lane >> 2, t4 = lane & 3;
    int wm = wid & 3, wn = wid >> 2;

    const unsigned* qb = g_qh + (size_t)(bh * L_ + i0) * 32;
    const unsigned* kb = g_kh + (size_t)(bh * L_ + j0) * 32;

    #pragma unroll
    for (int u = 0; u < 4; u++) {
        int id = u * 256 + tid;
        int row = id >> 3, seg = (id & 7) * 4;
        uint4 q = *reinterpret_cast<const uint4*>(qb + (size_t)row * 32 + seg);
        sQp[row * 33 + seg + 0] = q.x; sQp[row * 33 + seg + 1] = q.y;
        sQp[row * 33 + seg + 2] = q.z; sQp[row * 33 + seg + 3] = q.w;
        uint4 k = *reinterpret_cast<const uint4*>(kb + (size_t)row * 32 + seg);
        sKp[row * 33 + seg + 0] = k.x; sKp[row * 33 + seg + 1] = k.y;
        sKp[row * 33 + seg + 2] = k.z; sKp[row * 33 + seg + 3] = k.w;
    }
    __syncthreads();

    float acc[2][8][4];
    #pragma unroll
    for (int mt = 0; mt < 2; mt++)
        #pragma unroll
        for (int nt = 0; nt < 8; nt++)
            #pragma unroll
            for (int c = 0; c < 4; c++) acc[mt][nt][c] = 0.0f;

    #pragma unroll
    for (int s = 0; s < 4; s++) {
        int kb2 = s * 8;
        unsigned af[2][4];
        #pragma unroll
        for (int mt = 0; mt < 2; mt++) {
            int r = wm * 32 + mt * 16 + g;
            af[mt][0] = sQp[r * 33 + kb2 + t4];
            af[mt][1] = sQp[(r + 8) * 33 + kb2 + t4];
            af[mt][2] = sQp[r * 33 + kb2 + t4 + 4];
            af[mt][3] = sQp[(r + 8) * 33 + kb2 + t4 + 4];
        }
        #pragma unroll
        for (int nt = 0; nt < 8; nt++) {
            int n = wn * 64 + nt * 8 + g;
            unsigned b0 = sKp[n * 33 + kb2 + t4];
            unsigned b1 = sKp[n * 33 + kb2 + t4 + 4];
            #pragma unroll
            for (int mt = 0; mt < 2; mt++)
                mma_f16(acc[mt][nt][0], acc[mt][nt][1], acc[mt][nt][2], acc[mt][nt][3],
                        af[mt][0], af[mt][1], af[mt][2], af[mt][3], b0, b1);
        }
    }

    bool edge = (jt == it);
    #pragma unroll
    for (int mt = 0; mt < 2; mt++) {
        #pragma unroll
        for (int nt = 0; nt < 8; nt++) {
            #pragma unroll
            for (int half = 0; half < 2; half++) {
                int i = i0 + wm * 32 + mt * 16 + g + half * 8;
                int j = j0 + wn * 64 + nt * 8 + t4 * 2;
                float v0 = acc[mt][nt][half * 2] * 0.125f;
                float v1 = acc[mt][nt][half * 2 + 1] * 0.125f;
                if (edge) {
                    if (j > i) v0 = 0.0f;
                    if (j + 1 > i) v1 = 0.0f;
                }
                *reinterpret_cast<float2*>(g_s + (size_t)(bh * L_ + i) * L_ + j) =
                    make_float2(v0, v1);
            }
        }
    }
}

// ---------------- kernel 4: kerple + DAPE MLP (bf16 mma), 2 j-chunks per block ----------------
#define PC_ 18
__global__ void __launch_bounds__(256)
k_dape3(const float* __restrict__ w1, const float* __restrict__ b1,
        const float* __restrict__ w2, const float* __restrict__ b2) {
    int i = blockIdx.y;
    int b = blockIdx.z;
    int jbase = blockIdx.x * 256;
    if (jbase > i) return;

    __shared__ float sC[128 * 36];
    __shared__ unsigned sCb[128 * PC_];
    __shared__ unsigned sHb[128 * PC_];
    __shared__ unsigned w1p[16 * 33];
    __shared__ unsigned w2p[16 * 17];
    __shared__ float b1s[32], b2s[16];

    int tid = threadIdx.x;
    for (int t = tid; t < 512; t += 256) {
        int kp = t >> 5, n = t & 31;
        w1p[kp * 33 + n] = pk_bf16(w1[(2 * kp) * 32 + n], w1[(2 * kp + 1) * 32 + n]);
    }
    {
        int kp = tid >> 4, n = tid & 15;
        w2p[kp * 17 + n] = pk_bf16(w2[(2 * kp) * 16 + n], w2[(2 * kp + 1) * 16 + n]);
    }
    if (tid < 32) b1s[tid] = b1[tid];
    if (tid < 16) b2s[tid] = b2[tid];

    int lane = tid & 31, wid = tid >> 5;
    int g = lane >> 2, t4 = lane & 3;
    int r0 = wid * 16;
    __syncthreads();

    #pragma unroll
    for (int cc = 0; cc < 2; cc++) {
        int j0 = jbase + cc * 128;
        if (j0 > i) break;

        size_t off = (size_t)b * (H_ * L_ * L_) + (size_t)i * L_ + j0;
        if (tid < 128) {
            int r = tid;
            float c[16];
            #pragma unroll
            for (int h = 0; h < 16; h++) {
                c[h] = g_s[off + (size_t)h * (L_ * L_) + r];
                sC[r * 36 + h] = c[h];
            }
            #pragma unroll
            for (int p = 0; p < 8; p++)
                sCb[r * PC_ + p] = pk_bf16(c[2 * p], c[2 * p + 1]);
        } else {
            int r = tid - 128;
            int dist = i - (j0 + r);
            if (dist < 0) dist = 0;
            const float4* kt = reinterpret_cast<const float4*>(g_kt + dist * H_);
            float k[16];
            #pragma unroll
            for (int q = 0; q < 4; q++) {
                float4 v = kt[q];
                k[4 * q] = v.x; k[4 * q + 1] = v.y; k[4 * q + 2] = v.z; k[4 * q + 3] = v.w;
            }
            #pragma unroll
            for (int h = 0; h < 16; h++) sC[r * 36 + 16 + h] = k[h];
            #pragma unroll
            for (int p = 0; p < 8; p++)
                sCb[r * PC_ + 8 + p] = pk_bf16(k[2 * p], k[2 * p + 1]);
        }
        __syncthreads();

        float acc1[4][4];
        #pragma unroll
        for (int nt = 0; nt < 4; nt++)
            #pragma unroll
            for (int c = 0; c < 4; c++) acc1[nt][c] = 0.0f;
        #pragma unroll
        for (int ks = 0; ks < 2; ks++) {
            int kp = ks * 8;
            unsigned a0 = sCb[(r0 + g) * PC_ + kp + t4];
            unsigned a1 = sCb[(r0 + 8 + g) * PC_ + kp + t4];
            unsigned a2 = sCb[(r0 + g) * PC_ + kp + t4 + 4];
            unsigned a3 = sCb[(r0 + 8 + g) * PC_ + kp + t4 + 4];
            #pragma unroll
            for (int nt = 0; nt < 4; nt++) {
                int n = nt * 8 + g;
                unsigned b0 = w1p[(kp + t4) * 33 + n];
                unsigned b1f = w1p[(kp + t4 + 4) * 33 + n];
                mma_bf16(acc1[nt][0], acc1[nt][1], acc1[nt][2], acc1[nt][3],
                         a0, a1, a2, a3, b0, b1f);
            }
        }
        #pragma unroll
        for (int nt = 0; nt < 4; nt++)
            #pragma unroll
            for (int half = 0; half < 2; half++) {
                int row = r0 + g + half * 8;
                int col = nt * 8 + t4 * 2;
                float x0 = acc1[nt][half * 2 + 0] + b1s[col];
                float x1 = acc1[nt][half * 2 + 1] + b1s[col + 1];
                float g0 = 0.5f * x0 * (1.0f + erff(x0 * 0.70710678118f));
                float g1 = 0.5f * x1 * (1.0f + erff(x1 * 0.70710678118f));
                sHb[row * PC_ + nt * 4 + t4] = pk_bf16(g0, g1);
            }
        __syncwarp();

        float acc2[2][4];
        #pragma unroll
        for (int nt = 0; nt < 2; nt++)
            #pragma unroll
            for (int c = 0; c < 4; c++) acc2[nt][c] = 0.0f;
        #pragma unroll
        for (int ks = 0; ks < 2; ks++) {
            int kp = ks * 8;
            unsigned a0 = sHb[(r0 + g) * PC_ + kp + t4];
            unsigned a1 = sHb[(r0 + 8 + g) * PC_ + kp + t4];
            unsigned a2 = sHb[(r0 + g) * PC_ + kp + t4 + 4];
            unsigned a3 = sHb[(r0 + 8 + g) * PC_ + kp + t4 + 4];
            #pragma unroll
            for (int nt = 0; nt < 2; nt++) {
                int n = nt * 8 + g;
                unsigned b0 = w2p[(kp + t4) * 17 + n];
                unsigned b1f = w2p[(kp + t4 + 4) * 17 + n];
                mma_bf16(acc2[nt][0], acc2[nt][1], acc2[nt][2], acc2[nt][3],
                         a0, a1, a2, a3, b0, b1f);
            }
        }
        #pragma unroll
        for (int nt = 0; nt < 2; nt++)
            #pragma unroll
            for (int half = 0; half < 2; half++) {
                int row = r0 + g + half * 8;
                if (j0 + row <= i) {
                    #pragma unroll
                    for (int q = 0; q < 2; q++) {
                        int h = nt * 8 + t4 * 2 + q;
                        g_s[off + (size_t)h * (L_ * L_) + row] =
                            sC[row * 36 + h] + sC[row * 36 + 16 + h]
                            + acc2[nt][half * 2 + q] + b2s[h];
                    }
                }
            }
        __syncthreads();
    }
}

// ---------------- kernel 5: causal softmax per row -> fp16 weights in g_w ----------------
__global__ void k_softmax() {
    int row = blockIdx.x;
    int i = row & 1023;
    int n = i + 1;
    const float* S = g_s + (size_t)row * L_;
    __half* W = g_w + (size_t)row * L_;
    __shared__ float buf[1024];
    __shared__ float redm[4], reds[4];
    int tx = threadIdx.x;

    float m = -1e30f;
    for (int j2 = tx * 2; j2 < n; j2 += 256) {
        float2 v = *reinterpret_cast<const float2*>(S + j2);
        buf[j2] = v.x; m = fmaxf(m, v.x);
        if (j2 + 1 < n) { buf[j2 + 1] = v.y; m = fmaxf(m, v.y); }
    }
    #pragma unroll
    for (int o = 16; o; o >>= 1) m = fmaxf(m, __shfl_xor_sync(0xffffffffu, m, o));
    if ((tx & 31) == 0) redm[tx >> 5] = m;
    __syncthreads();
    m = fmaxf(fmaxf(redm[0], redm[1]), fmaxf(redm[2], redm[3]));

    float sum = 0.0f;
    for (int j2 = tx * 2; j2 < n; j2 += 256) {
        float e0 = expf(buf[j2] - m); buf[j2] = e0; sum += e0;
        if (j2 + 1 < n) { float e1 = expf(buf[j2 + 1] - m); buf[j2 + 1] = e1; sum += e1; }
    }
    #pragma unroll
    for (int o = 16; o; o >>= 1) sum += __shfl_xor_sync(0xffffffffu, sum, o);
    if ((tx & 31) == 0) reds[tx >> 5] = sum;
    __syncthreads();
    sum = reds[0] + reds[1] + reds[2] + reds[3];
    float inv = 1.0f / sum;
    for (int j2 = tx * 2; j2 < n; j2 += 256) {
        if (j2 + 1 < n)
            *reinterpret_cast<unsigned*>(W + j2) = pk_h(buf[j2] * inv, buf[j2 + 1] * inv);
        else
            W[j2] = __float2half_rn(buf[j2] * inv);
    }
}

// ---------------- kernel 6: out = weights @ v (fp16 mma) -> packed g_oh ----------------
__global__ void __launch_bounds__(256) k_pv_h() {
    int it = gridDim.x - 1 - blockIdx.x;
    int bh = blockIdx.y;
    __shared__ unsigned sWp[128 * 20];
    __shared__ unsigned sVp[64 * 20];
    int i0 = it * 128;
    int tid = threadIdx.x;
    int lane = tid & 31, wid = tid >> 5;
    int g = lane >> 2, t4 = lane & 3;
    int wm = wid & 3, wn = wid >> 2;

    float acc[2][4][4];
    #pragma unroll
    for (int mt = 0; mt < 2; mt++)
        #pragma unroll
        for (int nt = 0; nt < 4; nt++)
            #pragma unroll
            for (int c = 0; c < 4; c++) acc[mt][nt][c] = 0.0f;

    const unsigned* wbase = reinterpret_cast<const unsigned*>(g_w) + (size_t)(bh * L_ + i0) * (L_ / 2);
    const unsigned* vbase = g_vtp + (size_t)bh * D_ * (L_ / 2);
    int nch = (it + 1) * 4;

    uint4 rw[2];
    unsigned rv[4];
    #pragma unroll
    for (int u = 0; u < 2; u++) {
        int id = u * 256 + tid;
        int row = id >> 2, seg = id & 3;
        rw[u] = *reinterpret_cast<const uint4*>(wbase + (size_t)row * (L_ / 2) + seg * 4);
    }
    #pragma unroll
    for (int u = 0; u < 4; u++) {
        int id = u * 256 + tid;
        int d = id >> 4, kp = id & 15;
        rv[u] = vbase[(size_t)d * (L_ / 2) + kp];
    }

    for (int ch = 0; ch < nch; ch++) {
        #pragma unroll
        for (int u = 0; u < 2; u++) {
            int id = u * 256 + tid;
            int row = id >> 2, kpb = (id & 3) * 4;
            sWp[row * 20 + kpb + 0] = rw[u].x;
            sWp[row * 20 + kpb + 1] = rw[u].y;
            sWp[row * 20 + kpb + 2] = rw[u].z;
            sWp[row * 20 + kpb + 3] = rw[u].w;
        }
        #pragma unroll
        for (int u = 0; u < 4; u++) {
            int id = u * 256 + tid;
            int d = id >> 4, kp = id & 15;
            sVp[d * 20 + kp] = rv[u];
        }
        __syncthreads();

        if (ch + 1 < nch) {
            int jp = (ch + 1) * 16;
            #pragma unroll
            for (int u = 0; u < 2; u++) {
                int id = u * 256 + tid;
                int row = id >> 2, seg = id & 3;
                rw[u] = *reinterpret_cast<const uint4*>(wbase + (size_t)row * (L_ / 2) + jp + seg * 4);
            }
            #pragma unroll
            for (int u = 0; u < 4; u++) {
                int id = u * 256 + tid;
                int d = id >> 4, kp = id & 15;
                rv[u] = vbase[(size_t)d * (L_ / 2) + jp + kp];
            }
        }

        #pragma unroll
        for (int s = 0; s < 2; s++) {
            int kb = s * 8;
            unsigned af[2][4];
            #pragma unroll
            for (int mt = 0; mt < 2; mt++) {
                int r = wm * 32 + mt * 16 + g;
                af[mt][0] = sWp[r * 20 + kb + t4];
                af[mt][1] = sWp[(r + 8) * 20 + kb + t4];
                af[mt][2] = sWp[r * 20 + kb + t4 + 4];
                af[mt][3] = sWp[(r + 8) * 20 + kb + t4 + 4];
            }
            #pragma unroll
            for (int nt = 0; nt < 4; nt++) {
                int n = wn * 32 + nt * 8 + g;
                unsigned b0 = sVp[n * 20 + kb + t4];
                unsigned b1 = sVp[n * 20 + kb + t4 + 4];
                #pragma unroll
                for (int mt = 0; mt < 2; mt++)
                    mma_f16(acc[mt][nt][0], acc[mt][nt][1], acc[mt][nt][2], acc[mt][nt][3],
                            af[mt][0], af[mt][1], af[mt][2], af[mt][3], b0, b1);
            }
        }
        __syncthreads();
    }

    int b = bh >> 4, h = bh & 15;
    #pragma unroll
    for (int mt = 0; mt < 2; mt++)
        #pragma unroll
        for (int nt = 0; nt < 4; nt++)
            #pragma unroll
            for (int half = 0; half < 2; half++) {
                int i = i0 + wm * 32 + mt * 16 + g + half * 8;
                int dp = wn * 16 + nt * 4 + t4;
                g_oh[(size_t)(b * L_ + i) * 512 + h * 32 + dp] =
                    pk_h(acc[mt][nt][half * 2], acc[mt][nt][half * 2 + 1]);
            }
}

// ---------------- launch ----------------
extern "C" void kernel_launch(void* const* d_in, const int* in_sizes, int n_in,
                              void* d_out, int out_size) {
    const float* x     = (const float*)d_in[0];
    const float* w_qkv = (const float*)d_in[1];
    const float* w_o   = (const float*)d_in[2];
    const float* log_p = (const float*)d_in[3];
    const float* log_a = (const float*)d_in[4];
    const float* w1    = (const float*)d_in[5];
    const float* b1    = (const float*)d_in[6];
    const float* w2    = (const float*)d_in[7];
    const float* b2    = (const float*)d_in[8];
    float* y = (float*)d_out;

    void* xh_ptr = nullptr;  cudaGetSymbolAddress(&xh_ptr, g_xh);
    void* wq_ptr = nullptr;  cudaGetSymbolAddress(&wq_ptr, g_wqkvh);
    void* wo_ptr = nullptr;  cudaGetSymbolAddress(&wo_ptr, g_woh);
    void* oh_ptr = nullptr;  cudaGetSymbolAddress(&oh_ptr, g_oh);

    // 0. pack inputs to fp16
    k_packA<<<(M_ * HID_ / 2) / 256, 256>>>(x, (unsigned*)xh_ptr);
    k_packB<N3_><<<(HID_ / 2) * N3_ / 256, 256>>>(w_qkv, (unsigned*)wq_ptr);
    k_packB<HID_><<<(HID_ / 2) * HID_ / 256, 256>>>(w_o, (unsigned*)wo_ptr);

    // 1. QKV projection (packed fp16 mma, 64x64 tiles, high occupancy)
    k_gemm_hp<N3_, 1><<<dim3(N3_ / 64, M_ / 64), 128>>>((const unsigned*)xh_ptr, (const unsigned*)wq_ptr, nullptr);
    // 2. RoPE -> packed fp16 q/k; kerple table; V transpose
    k_rope2<<<(B_ * H_ * L_ * 32) / 256, 256>>>();
    k_ktab<<<4, 256>>>(log_p, log_a);
    k_vt<<<dim3(8, B_ * H_), 256>>>();
    // 3. scores (fp16 mma)
    k_scores_h<<<dim3(8, 8, B_ * H_), 256>>>();
    // 4. kerple + DAPE MLP
    k_dape3<<<dim3(4, L_, B_), 256>>>(w1, b1, w2, b2);
    // 5. softmax -> fp16 weights
    k_softmax<<<B_ * H_ * L_, 128>>>();
    // 6. PV -> packed fp16 g_oh
    k_pv_h<<<dim3(8, B_ * H_), 256>>>();
    // 7. output projection (packed fp16 mma, 64x64 tiles) -> y fp32
    k_gemm_hp<HID_, 0><<<dim3(HID_ / 64, M_ / 64), 128>>>((const unsigned*)oh_ptr, (const unsigned*)wo_ptr, y);
}

// round 15
// speedup vs baseline: 1.6639x; 1.6639x over previous
#include <cuda_runtime.h>
#include <cuda_fp16.h>
#include <math.h>

#define B_  2
#define L_  1024
#define H_  16
#define D_  64
#define HID_ 1024
#define N3_ 3072
#define HD_ 1024   // H*D
#define M_  2048   // B*L

// ---------------- scratch (device globals; no allocations) ----------------
__device__ float g_q[B_ * H_ * L_ * D_];   // fp32 post-QKV (pre-RoPE)
__device__ float g_k[B_ * H_ * L_ * D_];
__device__ float g_v[B_ * H_ * L_ * D_];
__device__ unsigned g_qh[B_ * H_ * L_ * (D_ / 2)];  // RoPE'd q, half2 packed along d
__device__ unsigned g_kh[B_ * H_ * L_ * (D_ / 2)];
__device__ float g_s[B_ * H_ * L_ * L_];   // raw scores, 128 MB
__device__ __half g_w[B_ * H_ * L_ * L_];  // softmax weights fp16 (zero-init above diag)
__device__ unsigned g_vtp[B_ * H_ * D_ * (L_ / 2)];  // V transposed, half2 packed along l
__device__ unsigned g_oh[M_ * (HD_ / 2)];  // attention out, half2 packed
__device__ float g_kt[L_ * H_];            // kerple table [dist][h]
__device__ unsigned g_xh[M_ * (HID_ / 2)];           // packed x
__device__ unsigned g_wqkvh[(HID_ / 2) * N3_];       // packed w_qkv [kp][n]
__device__ unsigned g_woh[(HID_ / 2) * HID_];        // packed w_o   [kp][n]

// ---------------- helpers ----------------
__device__ __forceinline__ unsigned pk_bf16(float lo, float hi) {
    unsigned r;
    asm("cvt.rn.bf16x2.f32 %0, %1, %2;" : "=r"(r) : "f"(hi), "f"(lo));
    return r;
}

__device__ __forceinline__ unsigned pk_h(float lo, float hi) {
    unsigned r;
    asm("cvt.rn.f16x2.f32 %0, %1, %2;" : "=r"(r) : "f"(hi), "f"(lo));
    return r;
}

__device__ __forceinline__ void mma_bf16(float& d0, float& d1, float& d2, float& d3,
                                         unsigned a0, unsigned a1, unsigned a2, unsigned a3,
                                         unsigned b0, unsigned b1) {
    asm volatile(
        "mma.sync.aligned.m16n8k16.row.col.f32.bf16.bf16.f32 "
        "{%0,%1,%2,%3}, {%4,%5,%6,%7}, {%8,%9}, {%0,%1,%2,%3};"
        : "+f"(d0), "+f"(d1), "+f"(d2), "+f"(d3)
        : "r"(a0), "r"(a1), "r"(a2), "r"(a3), "r"(b0), "r"(b1));
}

__device__ __forceinline__ void mma_f16(float& d0, float& d1, float& d2, float& d3,
                                        unsigned a0, unsigned a1, unsigned a2, unsigned a3,
                                        unsigned b0, unsigned b1) {
    asm volatile(
        "mma.sync.aligned.m16n8k16.row.col.f32.f16.f16.f32 "
        "{%0,%1,%2,%3}, {%4,%5,%6,%7}, {%8,%9}, {%0,%1,%2,%3};"
        : "+f"(d0), "+f"(d1), "+f"(d2), "+f"(d3)
        : "r"(a0), "r"(a1), "r"(a2), "r"(a3), "r"(b0), "r"(b1));
}

__device__ __forceinline__ void cp16(unsigned* smem, const unsigned* gmem) {
    unsigned saddr = (unsigned)__cvta_generic_to_shared(smem);
    asm volatile("cp.async.cg.shared.global [%0], [%1], 16;\n" :: "r"(saddr), "l"(gmem));
}
#define CP_COMMIT() asm volatile("cp.async.commit_group;\n" ::: "memory")
#define CP_WAIT1()  asm volatile("cp.async.wait_group 1;\n" ::: "memory")

// ---------------- pack kernels ----------------
__global__ void k_packA(const float* __restrict__ in, unsigned* __restrict__ out) {
    int t = blockIdx.x * 256 + threadIdx.x;
    float2 v = reinterpret_cast<const float2*>(in)[t];
    out[t] = pk_h(v.x, v.y);
}

template<int N>
__global__ void k_packB(const float* __restrict__ in, unsigned* __restrict__ out) {
    int t = blockIdx.x * 256 + threadIdx.x;
    int kp = t / N, n = t - kp * N;
    out[t] = pk_h(in[(size_t)(2 * kp) * N + n], in[(size_t)(2 * kp + 1) * N + n]);
}

// ---------------- packed fp16 GEMM, cp.async double buffer, BM=128 BN=128 BK=32 ----------------
template<int NLD, int MODE>
__global__ void __launch_bounds__(256)
k_gemm_hp(const unsigned* __restrict__ A, const unsigned* __restrict__ Bm, float* __restrict__ C) {
    __shared__ unsigned sAp[2][128 * 20];
    __shared__ unsigned sBp[2][16 * 132];

    int tid = threadIdx.x;
    int lane = tid & 31, wid = tid >> 5;
    int g = lane >> 2, t4 = lane & 3;
    int wm = wid & 3, wn = wid >> 2;
    int m0 = blockIdx.y * 128, n0 = blockIdx.x * 128;

    float acc[2][8][4];
    #pragma unroll
    for (int mt = 0; mt < 2; mt++)
        #pragma unroll
        for (int nt = 0; nt < 8; nt++)
            #pragma unroll
            for (int c = 0; c < 4; c++) acc[mt][nt][c] = 0.0f;

    // per-thread copy coordinates (fixed across stages)
    int arow = tid >> 2, aseg = (tid & 3) * 4;                 // A: 256 threads x (2 u) cover 128x16
    int bkp = tid >> 5, bn4 = (tid & 31) * 4;

    #define ISSUE(ch, buf)                                                                  \
        do {                                                                                \
            int kk = (ch) * 16;                                                             \
            cp16(&sAp[buf][arow * 20 + aseg], A + (size_t)(m0 + arow) * 512 + kk + aseg);   \
            cp16(&sAp[buf][(arow + 64) * 20 + aseg],                                        \
                 A + (size_t)(m0 + arow + 64) * 512 + kk + aseg);                           \
            cp16(&sBp[buf][bkp * 132 + bn4], Bm + (size_t)(kk + bkp) * NLD + n0 + bn4);     \
            cp16(&sBp[buf][(bkp + 8) * 132 + bn4],                                          \
                 Bm + (size_t)(kk + bkp + 8) * NLD + n0 + bn4);                             \
        } while (0)

    ISSUE(0, 0); CP_COMMIT();
    ISSUE(1, 1); CP_COMMIT();

    for (int ch = 0; ch < 32; ch++) {
        CP_WAIT1();
        __syncthreads();
        int buf = ch & 1;

        #pragma unroll
        for (int s = 0; s < 2; s++) {
            int kb = s * 8;
            unsigned af[2][4];
            #pragma unroll
            for (int mt = 0; mt < 2; mt++) {
                int r = wm * 32 + mt * 16 + g;
                af[mt][0] = sAp[buf][r * 20 + kb + t4];
                af[mt][1] = sAp[buf][(r + 8) * 20 + kb + t4];
                af[mt][2] = sAp[buf][r * 20 + kb + t4 + 4];
                af[mt][3] = sAp[buf][(r + 8) * 20 + kb + t4 + 4];
            }
            #pragma unroll
            for (int nt = 0; nt < 8; nt++) {
                int n = wn * 64 + nt * 8 + g;
                unsigned b0 = sBp[buf][(kb + t4) * 132 + n];
                unsigned b1 = sBp[buf][(kb + t4 + 4) * 132 + n];
                #pragma unroll
                for (int mt = 0; mt < 2; mt++)
                    mma_f16(acc[mt][nt][0], acc[mt][nt][1], acc[mt][nt][2], acc[mt][nt][3],
                            af[mt][0], af[mt][1], af[mt][2], af[mt][3], b0, b1);
            }
        }
        __syncthreads();
        if (ch + 2 < 32) ISSUE(ch + 2, buf);
        CP_COMMIT();
    }
    #undef ISSUE

    #pragma unroll
    for (int mt = 0; mt < 2; mt++) {
        #pragma unroll
        for (int nt = 0; nt < 8; nt++) {
            int row = m0 + wm * 32 + mt * 16 + g;
            int col = n0 + wn * 64 + nt * 8 + t4 * 2;
            if (MODE == 0) {
                *reinterpret_cast<float2*>(C + (size_t)row * NLD + col) =
                    make_float2(acc[mt][nt][0], acc[mt][nt][1]);
                *reinterpret_cast<float2*>(C + (size_t)(row + 8) * NLD + col) =
                    make_float2(acc[mt][nt][2], acc[mt][nt][3]);
            } else {
                #pragma unroll
                for (int half = 0; half < 2; half++) {
                    int m = row + half * 8;
                    int b = m >> 10, l = m & 1023;
                    int s = col >> 10, rem = col & 1023;
                    int h = rem >> 6, d = rem & 63;
                    float* dst = (s == 0) ? g_q : (s == 1) ? g_k : g_v;
                    *reinterpret_cast<float2*>(dst + (size_t)((b * H_ + h) * L_ + l) * D_ + d) =
                        make_float2(acc[mt][nt][half * 2], acc[mt][nt][half * 2 + 1]);
                }
            }
        }
    }
}

// ---------------- kernel 2: RoPE -> packed fp16 q/k ----------------
__global__ void k_rope2() {
    int t = blockIdx.x * 256 + threadIdx.x;
    int bh = t >> 15;
    int rem = t & 32767;
    int l = rem >> 5;
    int j = rem & 31;
    float invf = expf(-(float)j * (logf(10000.0f) / 32.0f));
    float ang = (float)l * invf;
    float cs = cosf(ang), sn = sinf(ang);
    int base = (bh << 16) + (l << 6) + j;
    float q1 = g_q[base], q2 = g_q[base + 32];
    float qa = q1 * cs - q2 * sn;
    float qb = q2 * cs + q1 * sn;
    float k1 = g_k[base], k2 = g_k[base + 32];
    float ka = k1 * cs - k2 * sn;
    float kb = k2 * cs + k1 * sn;

    float qan = __shfl_down_sync(0xffffffffu, qa, 1);
    float qbn = __shfl_down_sync(0xffffffffu, qb, 1);
    float kan = __shfl_down_sync(0xffffffffu, ka, 1);
    float kbn = __shfl_down_sync(0xffffffffu, kb, 1);
    if ((j & 1) == 0) {
        int rowo = (bh << 10) + l;
        int p = j >> 1;
        g_qh[rowo * 32 + p]      = pk_h(qa, qan);
        g_qh[rowo * 32 + 16 + p] = pk_h(qb, qbn);
        g_kh[rowo * 32 + p]      = pk_h(ka, kan);
        g_kh[rowo * 32 + 16 + p] = pk_h(kb, kbn);
    }
}

// ---------------- kernel 2b: kerple table [dist][h] ----------------
__global__ void k_ktab(const float* __restrict__ log_p, const float* __restrict__ log_a) {
    int d = blockIdx.x * 256 + threadIdx.x;
    if (d >= L_) return;
    float dist = (float)d;
    #pragma unroll
    for (int h = 0; h < H_; h++) {
        float p = log1pf(expf(log_p[h]));
        float a = log1pf(expf(log_a[h]));
        g_kt[d * H_ + h] = -p * log1pf(a * dist);
    }
}

// ---------------- kernel 2c: transpose V -> g_vtp[bh][d][l/2] half2 ----------------
__global__ void __launch_bounds__(256) k_vt() {
    int lb = blockIdx.x;
    int bh = blockIdx.y;
    __shared__ float sT[128][65];
    int tid = threadIdx.x;
    const float* vb = g_v + ((size_t)bh * L_ + lb * 128) * D_;
    #pragma unroll
    for (int u = 0; u < 8; u++) {
        int id = u * 256 + tid;
        int l = id >> 4, c4 = (id & 15) * 4;
        float4 v = *reinterpret_cast<const float4*>(vb + l * D_ + c4);
        sT[l][c4] = v.x; sT[l][c4 + 1] = v.y; sT[l][c4 + 2] = v.z; sT[l][c4 + 3] = v.w;
    }
    __syncthreads();
    unsigned* out = g_vtp + (size_t)bh * D_ * (L_ / 2) + lb * 64;
    #pragma unroll
    for (int u = 0; u < 16; u++) {
        int id = u * 256 + tid;
        int d = id >> 6, lp = id & 63;
        out[(size_t)d * (L_ / 2) + lp] = pk_h(sT[2 * lp][d], sT[2 * lp + 1][d]);
    }
}

// ---------------- kernel 3: scores = q k^T * scale (fp16 mma, 128x128, single-shot D) ----------------
__global__ void __launch_bounds__(256) k_scores_h() {
    int jt = blockIdx.x, it = blockIdx.y, bh = blockIdx.z;
    if (jt > it) return;
    int i0 = it * 128, j0 = jt * 128;
    __shared__ unsigned sQp[128 * 33];
    __shared__ unsigned sKp[128 * 33];

    int tid = threadIdx.x;
    int lane = tid & 31, wid = tid >> 5;
    int g = lane >> 2, t4 = lane & 3;
    int wm = wid & 3, wn = wid >> 2;

    const unsigned* qb = g_qh + (size_t)(bh * L_ + i0) * 32;
    const unsigned* kb = g_kh + (size_t)(bh * L_ + j0) * 32;

    #pragma unroll
    for (int u = 0; u < 4; u++) {
        int id = u * 256 + tid;
        int row = id >> 3, seg = (id & 7) * 4;
        uint4 q = *reinterpret_cast<const uint4*>(qb + (size_t)row * 32 + seg);
        sQp[row * 33 + seg + 0] = q.x; sQp[row * 33 + seg + 1] = q.y;
        sQp[row * 33 + seg + 2] = q.z; sQp[row * 33 + seg + 3] = q.w;
        uint4 k = *reinterpret_cast<const uint4*>(kb + (size_t)row * 32 + seg);
        sKp[row * 33 + seg + 0] = k.x; sKp[row * 33 + seg + 1] = k.y;
        sKp[row * 33 + seg + 2] = k.z; sKp[row * 33 + seg + 3] = k.w;
    }
    __syncthreads();

    float acc[2][8][4];
    #pragma unroll
    for (int mt = 0; mt < 2; mt++)
        #pragma unroll
        for (int nt = 0; nt < 8; nt++)
            #pragma unroll
            for (int c = 0; c < 4; c++) acc[mt][nt][c] = 0.0f;

    #pragma unroll
    for (int s = 0; s < 4; s++) {
        int kb2 = s * 8;
        unsigned af[2][4];
        #pragma unroll
        for (int mt = 0; mt < 2; mt++) {
            int r = wm * 32 + mt * 16 + g;
            af[mt][0] = sQp[r * 33 + kb2 + t4];
            af[mt][1] = sQp[(r + 8) * 33 + kb2 + t4];
            af[mt][2] = sQp[r * 33 + kb2 + t4 + 4];
            af[mt][3] = sQp[(r + 8) * 33 + kb2 + t4 + 4];
        }
        #pragma unroll
        for (int nt = 0; nt < 8; nt++) {
            int n = wn * 64 + nt * 8 + g;
            unsigned b0 = sKp[n * 33 + kb2 + t4];
            unsigned b1 = sKp[n * 33 + kb2 + t4 + 4];
            #pragma unroll
            for (int mt = 0; mt < 2; mt++)
                mma_f16(acc[mt][nt][0], acc[mt][nt][1], acc[mt][nt][2], acc[mt][nt][3],
                        af[mt][0], af[mt][1], af[mt][2], af[mt][3], b0, b1);
        }
    }

    bool edge = (jt == it);
    #pragma unroll
    for (int mt = 0; mt < 2; mt++) {
        #pragma unroll
        for (int nt = 0; nt < 8; nt++) {
            #pragma unroll
            for (int half = 0; half < 2; half++) {
                int i = i0 + wm * 32 + mt * 16 + g + half * 8;
                int j = j0 + wn * 64 + nt * 8 + t4 * 2;
                float v0 = acc[mt][nt][half * 2] * 0.125f;
                float v1 = acc[mt][nt][half * 2 + 1] * 0.125f;
                if (edge) {
                    if (j > i) v0 = 0.0f;
                    if (j + 1 > i) v1 = 0.0f;
                }
                *reinterpret_cast<float2*>(g_s + (size_t)(bh * L_ + i) * L_ + j) =
                    make_float2(v0, v1);
            }
        }
    }
}

// ---------------- kernel 4: kerple + DAPE MLP (bf16 mma), 2 j-chunks per block ----------------
#define PC_ 18
__global__ void __launch_bounds__(256)
k_dape3(const float* __restrict__ w1, const float* __restrict__ b1,
        const float* __restrict__ w2, const float* __restrict__ b2) {
    int i = blockIdx.y;
    int b = blockIdx.z;
    int jbase = blockIdx.x * 256;
    if (jbase > i) return;

    __shared__ float sC[128 * 36];
    __shared__ unsigned sCb[128 * PC_];
    __shared__ unsigned sHb[128 * PC_];
    __shared__ unsigned w1p[16 * 33];
    __shared__ unsigned w2p[16 * 17];
    __shared__ float b1s[32], b2s[16];

    int tid = threadIdx.x;
    for (int t = tid; t < 512; t += 256) {
        int kp = t >> 5, n = t & 31;
        w1p[kp * 33 + n] = pk_bf16(w1[(2 * kp) * 32 + n], w1[(2 * kp + 1) * 32 + n]);
    }
    {
        int kp = tid >> 4, n = tid & 15;
        w2p[kp * 17 + n] = pk_bf16(w2[(2 * kp) * 16 + n], w2[(2 * kp + 1) * 16 + n]);
    }
    if (tid < 32) b1s[tid] = b1[tid];
    if (tid < 16) b2s[tid] = b2[tid];

    int lane = tid & 31, wid = tid >> 5;
    int g = lane >> 2, t4 = lane & 3;
    int r0 = wid * 16;
    __syncthreads();

    #pragma unroll
    for (int cc = 0; cc < 2; cc++) {
        int j0 = jbase + cc * 128;
        if (j0 > i) break;

        size_t off = (size_t)b * (H_ * L_ * L_) + (size_t)i * L_ + j0;
        if (tid < 128) {
            int r = tid;
            float c[16];
            #pragma unroll
            for (int h = 0; h < 16; h++) {
                c[h] = g_s[off + (size_t)h * (L_ * L_) + r];
                sC[r * 36 + h] = c[h];
            }
            #pragma unroll
            for (int p = 0; p < 8; p++)
                sCb[r * PC_ + p] = pk_bf16(c[2 * p], c[2 * p + 1]);
        } else {
            int r = tid - 128;
            int dist = i - (j0 + r);
            if (dist < 0) dist = 0;
            const float4* kt = reinterpret_cast<const float4*>(g_kt + dist * H_);
            float k[16];
            #pragma unroll
            for (int q = 0; q < 4; q++) {
                float4 v = kt[q];
                k[4 * q] = v.x; k[4 * q + 1] = v.y; k[4 * q + 2] = v.z; k[4 * q + 3] = v.w;
            }
            #pragma unroll
            for (int h = 0; h < 16; h++) sC[r * 36 + 16 + h] = k[h];
            #pragma unroll
            for (int p = 0; p < 8; p++)
                sCb[r * PC_ + 8 + p] = pk_bf16(k[2 * p], k[2 * p + 1]);
        }
        __syncthreads();

        float acc1[4][4];
        #pragma unroll
        for (int nt = 0; nt < 4; nt++)
            #pragma unroll
            for (int c = 0; c < 4; c++) acc1[nt][c] = 0.0f;
        #pragma unroll
        for (int ks = 0; ks < 2; ks++) {
            int kp = ks * 8;
            unsigned a0 = sCb[(r0 + g) * PC_ + kp + t4];
            unsigned a1 = sCb[(r0 + 8 + g) * PC_ + kp + t4];
            unsigned a2 = sCb[(r0 + g) * PC_ + kp + t4 + 4];
            unsigned a3 = sCb[(r0 + 8 + g) * PC_ + kp + t4 + 4];
            #pragma unroll
            for (int nt = 0; nt < 4; nt++) {
                int n = nt * 8 + g;
                unsigned b0 = w1p[(kp + t4) * 33 + n];
                unsigned b1f = w1p[(kp + t4 + 4) * 33 + n];
                mma_bf16(acc1[nt][0], acc1[nt][1], acc1[nt][2], acc1[nt][3],
                         a0, a1, a2, a3, b0, b1f);
            }
        }
        #pragma unroll
        for (int nt = 0; nt < 4; nt++)
            #pragma unroll
            for (int half = 0; half < 2; half++) {
                int row = r0 + g + half * 8;
                int col = nt * 8 + t4 * 2;
                float x0 = acc1[nt][half * 2 + 0] + b1s[col];
                float x1 = acc1[nt][half * 2 + 1] + b1s[col + 1];
                float g0 = 0.5f * x0 * (1.0f + erff(x0 * 0.70710678118f));
                float g1 = 0.5f * x1 * (1.0f + erff(x1 * 0.70710678118f));
                sHb[row * PC_ + nt * 4 + t4] = pk_bf16(g0, g1);
            }
        __syncwarp();

        float acc2[2][4];
        #pragma unroll
        for (int nt = 0; nt < 2; nt++)
            #pragma unroll
            for (int c = 0; c < 4; c++) acc2[nt][c] = 0.0f;
        #pragma unroll
        for (int ks = 0; ks < 2; ks++) {
            int kp = ks * 8;
            unsigned a0 = sHb[(r0 + g) * PC_ + kp + t4];
            unsigned a1 = sHb[(r0 + 8 + g) * PC_ + kp + t4];
            unsigned a2 = sHb[(r0 + g) * PC_ + kp + t4 + 4];
            unsigned a3 = sHb[(r0 + 8 + g) * PC_ + kp + t4 + 4];
            #pragma unroll
            for (int nt = 0; nt < 2; nt++) {
                int n = nt * 8 + g;
                unsigned b0 = w2p[(kp + t4) * 17 + n];
                unsigned b1f = w2p[(kp + t4 + 4) * 17 + n];
                mma_bf16(acc2[nt][0], acc2[nt][1], acc2[nt][2], acc2[nt][3],
                         a0, a1, a2, a3, b0, b1f);
            }
        }
        #pragma unroll
        for (int nt = 0; nt < 2; nt++)
            #pragma unroll
            for (int half = 0; half < 2; half++) {
                int row = r0 + g + half * 8;
                if (j0 + row <= i) {
                    #pragma unroll
                    for (int q = 0; q < 2; q++) {
                        int h = nt * 8 + t4 * 2 + q;
                        g_s[off + (size_t)h * (L_ * L_) + row] =
                            sC[row * 36 + h] + sC[row * 36 + 16 + h]
                            + acc2[nt][half * 2 + q] + b2s[h];
                    }
                }
            }
        __syncthreads();
    }
}

// ---------------- kernel 5: causal softmax per row -> fp16 weights in g_w ----------------
__global__ void k_softmax() {
    int row = blockIdx.x;
    int i = row & 1023;
    int n = i + 1;
    const float* S = g_s + (size_t)row * L_;
    __half* W = g_w + (size_t)row * L_;
    __shared__ float buf[1024];
    __shared__ float redm[4], reds[4];
    int tx = threadIdx.x;

    float m = -1e30f;
    for (int j2 = tx * 2; j2 < n; j2 += 256) {
        float2 v = *reinterpret_cast<const float2*>(S + j2);
        buf[j2] = v.x; m = fmaxf(m, v.x);
        if (j2 + 1 < n) { buf[j2 + 1] = v.y; m = fmaxf(m, v.y); }
    }
    #pragma unroll
    for (int o = 16; o; o >>= 1) m = fmaxf(m, __shfl_xor_sync(0xffffffffu, m, o));
    if ((tx & 31) == 0) redm[tx >> 5] = m;
    __syncthreads();
    m = fmaxf(fmaxf(redm[0], redm[1]), fmaxf(redm[2], redm[3]));

    float sum = 0.0f;
    for (int j2 = tx * 2; j2 < n; j2 += 256) {
        float e0 = expf(buf[j2] - m); buf[j2] = e0; sum += e0;
        if (j2 + 1 < n) { float e1 = expf(buf[j2 + 1] - m); buf[j2 + 1] = e1; sum += e1; }
    }
    #pragma unroll
    for (int o = 16; o; o >>= 1) sum += __shfl_xor_sync(0xffffffffu, sum, o);
    if ((tx & 31) == 0) reds[tx >> 5] = sum;
    __syncthreads();
    sum = reds[0] + reds[1] + reds[2] + reds[3];
    float inv = 1.0f / sum;
    for (int j2 = tx * 2; j2 < n; j2 += 256) {
        if (j2 + 1 < n)
            *reinterpret_cast<unsigned*>(W + j2) = pk_h(buf[j2] * inv, buf[j2 + 1] * inv);
        else
            W[j2] = __float2half_rn(buf[j2] * inv);
    }
}

// ---------------- kernel 6: out = weights @ v (fp16 mma) -> packed g_oh ----------------
__global__ void __launch_bounds__(256) k_pv_h() {
    int it = gridDim.x - 1 - blockIdx.x;
    int bh = blockIdx.y;
    __shared__ unsigned sWp[128 * 20];
    __shared__ unsigned sVp[64 * 20];
    int i0 = it * 128;
    int tid = threadIdx.x;
    int lane = tid & 31, wid = tid >> 5;
    int g = lane >> 2, t4 = lane & 3;
    int wm = wid & 3, wn = wid >> 2;

    float acc[2][4][4];
    #pragma unroll
    for (int mt = 0; mt < 2; mt++)
        #pragma unroll
        for (int nt = 0; nt < 4; nt++)
            #pragma unroll
            for (int c = 0; c < 4; c++) acc[mt][nt][c] = 0.0f;

    const unsigned* wbase = reinterpret_cast<const unsigned*>(g_w) + (size_t)(bh * L_ + i0) * (L_ / 2);
    const unsigned* vbase = g_vtp + (size_t)bh * D_ * (L_ / 2);
    int nch = (it + 1) * 4;

    uint4 rw[2];
    unsigned rv[4];
    #pragma unroll
    for (int u = 0; u < 2; u++) {
        int id = u * 256 + tid;
        int row = id >> 2, seg = id & 3;
        rw[u] = *reinterpret_cast<const uint4*>(wbase + (size_t)row * (L_ / 2) + seg * 4);
    }
    #pragma unroll
    for (int u = 0; u < 4; u++) {
        int id = u * 256 + tid;
        int d = id >> 4, kp = id & 15;
        rv[u] = vbase[(size_t)d * (L_ / 2) + kp];
    }

    for (int ch = 0; ch < nch; ch++) {
        #pragma unroll
        for (int u = 0; u < 2; u++) {
            int id = u * 256 + tid;
            int row = id >> 2, kpb = (id & 3) * 4;
            sWp[row * 20 + kpb + 0] = rw[u].x;
            sWp[row * 20 + kpb + 1] = rw[u].y;
            sWp[row * 20 + kpb + 2] = rw[u].z;
            sWp[row * 20 + kpb + 3] = rw[u].w;
        }
        #pragma unroll
        for (int u = 0; u < 4; u++) {
            int id = u * 256 + tid;
            int d = id >> 4, kp = id & 15;
            sVp[d * 20 + kp] = rv[u];
        }
        __syncthreads();

        if (ch + 1 < nch) {
            int jp = (ch + 1) * 16;
            #pragma unroll
            for (int u = 0; u < 2; u++) {
                int id = u * 256 + tid;
                int row = id >> 2, seg = id & 3;
                rw[u] = *reinterpret_cast<const uint4*>(wbase + (size_t)row * (L_ / 2) + jp + seg * 4);
            }
            #pragma unroll
            for (int u = 0; u < 4; u++) {
                int id = u * 256 + tid;
                int d = id >> 4, kp = id & 15;
                rv[u] = vbase[(size_t)d * (L_ / 2) + jp + kp];
            }
        }

        #pragma unroll
        for (int s = 0; s < 2; s++) {
            int kb = s * 8;
            unsigned af[2][4];
            #pragma unroll
            for (int mt = 0; mt < 2; mt++) {
                int r = wm * 32 + mt * 16 + g;
                af[mt][0] = sWp[r * 20 + kb + t4];
                af[mt][1] = sWp[(r + 8) * 20 + kb + t4];
                af[mt][2] = sWp[r * 20 + kb + t4 + 4];
                af[mt][3] = sWp[(r + 8) * 20 + kb + t4 + 4];
            }
            #pragma unroll
            for (int nt = 0; nt < 4; nt++) {
                int n = wn * 32 + nt * 8 + g;
                unsigned b0 = sVp[n * 20 + kb + t4];
                unsigned b1 = sVp[n * 20 + kb + t4 + 4];
                #pragma unroll
                for (int mt = 0; mt < 2; mt++)
                    mma_f16(acc[mt][nt][0], acc[mt][nt][1], acc[mt][nt][2], acc[mt][nt][3],
                            af[mt][0], af[mt][1], af[mt][2], af[mt][3], b0, b1);
            }
        }
        __syncthreads();
    }

    int b = bh >> 4, h = bh & 15;
    #pragma unroll
    for (int mt = 0; mt < 2; mt++)
        #pragma unroll
        for (int nt = 0; nt < 4; nt++)
            #pragma unroll
            for (int half = 0; half < 2; half++) {
                int i = i0 + wm * 32 + mt * 16 + g + half * 8;
                int dp = wn * 16 + nt * 4 + t4;
                g_oh[(size_t)(b * L_ + i) * 512 + h * 32 + dp] =
                    pk_h(acc[mt][nt][half * 2], acc[mt][nt][half * 2 + 1]);
            }
}

// ---------------- launch ----------------
extern "C" void kernel_launch(void* const* d_in, const int* in_sizes, int n_in,
                              void* d_out, int out_size) {
    const float* x     = (const float*)d_in[0];
    const float* w_qkv = (const float*)d_in[1];
    const float* w_o   = (const float*)d_in[2];
    const float* log_p = (const float*)d_in[3];
    const float* log_a = (const float*)d_in[4];
    const float* w1    = (const float*)d_in[5];
    const float* b1    = (const float*)d_in[6];
    const float* w2    = (const float*)d_in[7];
    const float* b2    = (const float*)d_in[8];
    float* y = (float*)d_out;

    void* xh_ptr = nullptr;  cudaGetSymbolAddress(&xh_ptr, g_xh);
    void* wq_ptr = nullptr;  cudaGetSymbolAddress(&wq_ptr, g_wqkvh);
    void* wo_ptr = nullptr;  cudaGetSymbolAddress(&wo_ptr, g_woh);
    void* oh_ptr = nullptr;  cudaGetSymbolAddress(&oh_ptr, g_oh);

    // 0. pack inputs to fp16
    k_packA<<<(M_ * HID_ / 2) / 256, 256>>>(x, (unsigned*)xh_ptr);
    k_packB<N3_><<<(HID_ / 2) * N3_ / 256, 256>>>(w_qkv, (unsigned*)wq_ptr);
    k_packB<HID_><<<(HID_ / 2) * HID_ / 256, 256>>>(w_o, (unsigned*)wo_ptr);

    // 1. QKV projection (packed fp16 mma, cp.async double buffer)
    k_gemm_hp<N3_, 1><<<dim3(N3_ / 128, M_ / 128), 256>>>((const unsigned*)xh_ptr, (const unsigned*)wq_ptr, nullptr);
    // 2. RoPE -> packed fp16 q/k; kerple table; V transpose
    k_rope2<<<(B_ * H_ * L_ * 32) / 256, 256>>>();
    k_ktab<<<4, 256>>>(log_p, log_a);
    k_vt<<<dim3(8, B_ * H_), 256>>>();
    // 3. scores (fp16 mma)
    k_scores_h<<<dim3(8, 8, B_ * H_), 256>>>();
    // 4. kerple + DAPE MLP
    k_dape3<<<dim3(4, L_, B_), 256>>>(w1, b1, w2, b2);
    // 5. softmax -> fp16 weights
    k_softmax<<<B_ * H_ * L_, 128>>>();
    // 6. PV -> packed fp16 g_oh
    k_pv_h<<<dim3(8, B_ * H_), 256>>>();
    // 7. output projection (packed fp16 mma, cp.async double buffer) -> y fp32
    k_gemm_hp<HID_, 0><<<dim3(HID_ / 128, M_ / 128), 256>>>((const unsigned*)oh_ptr, (const unsigned*)wo_ptr, y);
}

// round 16
// speedup vs baseline: 1.6758x; 1.0071x over previous
#include <cuda_runtime.h>
#include <cuda_fp16.h>
#include <math.h>

#define B_  2
#define L_  1024
#define H_  16
#define D_  64
#define HID_ 1024
#define N3_ 3072
#define HD_ 1024   // H*D
#define M_  2048   // B*L

// ---------------- scratch (device globals; no allocations) ----------------
__device__ float g_q[B_ * H_ * L_ * D_];   // fp32 post-QKV (pre-RoPE)
__device__ float g_k[B_ * H_ * L_ * D_];
__device__ float g_v[B_ * H_ * L_ * D_];
__device__ unsigned g_qh[B_ * H_ * L_ * (D_ / 2)];  // RoPE'd q, half2 packed along d
__device__ unsigned g_kh[B_ * H_ * L_ * (D_ / 2)];
__device__ float g_s[B_ * H_ * L_ * L_];   // raw scores, 128 MB
__device__ __half g_w[B_ * H_ * L_ * L_];  // softmax weights fp16 (zero-init above diag)
__device__ unsigned g_vtp[B_ * H_ * D_ * (L_ / 2)];  // V transposed, half2 packed along l
__device__ unsigned g_oh[M_ * (HD_ / 2)];  // attention out, half2 packed
__device__ float g_kt[L_ * H_];            // kerple table [dist][h]
__device__ unsigned g_xh[M_ * (HID_ / 2)];           // packed x
__device__ unsigned g_wqkvh[(HID_ / 2) * N3_];       // packed w_qkv [kp][n]
__device__ unsigned g_woh[(HID_ / 2) * HID_];        // packed w_o   [kp][n]

// ---------------- helpers ----------------
__device__ __forceinline__ unsigned pk_bf16(float lo, float hi) {
    unsigned r;
    asm("cvt.rn.bf16x2.f32 %0, %1, %2;" : "=r"(r) : "f"(hi), "f"(lo));
    return r;
}

__device__ __forceinline__ unsigned pk_h(float lo, float hi) {
    unsigned r;
    asm("cvt.rn.f16x2.f32 %0, %1, %2;" : "=r"(r) : "f"(hi), "f"(lo));
    return r;
}

__device__ __forceinline__ void mma_bf16(float& d0, float& d1, float& d2, float& d3,
                                         unsigned a0, unsigned a1, unsigned a2, unsigned a3,
                                         unsigned b0, unsigned b1) {
    asm volatile(
        "mma.sync.aligned.m16n8k16.row.col.f32.bf16.bf16.f32 "
        "{%0,%1,%2,%3}, {%4,%5,%6,%7}, {%8,%9}, {%0,%1,%2,%3};"
        : "+f"(d0), "+f"(d1), "+f"(d2), "+f"(d3)
        : "r"(a0), "r"(a1), "r"(a2), "r"(a3), "r"(b0), "r"(b1));
}

__device__ __forceinline__ void mma_f16(float& d0, float& d1, float& d2, float& d3,
                                        unsigned a0, unsigned a1, unsigned a2, unsigned a3,
                                        unsigned b0, unsigned b1) {
    asm volatile(
        "mma.sync.aligned.m16n8k16.row.col.f32.f16.f16.f32 "
        "{%0,%1,%2,%3}, {%4,%5,%6,%7}, {%8,%9}, {%0,%1,%2,%3};"
        : "+f"(d0), "+f"(d1), "+f"(d2), "+f"(d3)
        : "r"(a0), "r"(a1), "r"(a2), "r"(a3), "r"(b0), "r"(b1));
}

__device__ __forceinline__ void cp16(unsigned* smem, const unsigned* gmem) {
    unsigned saddr = (unsigned)__cvta_generic_to_shared(smem);
    asm volatile("cp.async.cg.shared.global [%0], [%1], 16;\n" :: "r"(saddr), "l"(gmem));
}
#define CP_COMMIT() asm volatile("cp.async.commit_group;\n" ::: "memory")
#define CP_WAIT1()  asm volatile("cp.async.wait_group 1;\n" ::: "memory")

// ---------------- pack kernels ----------------
__global__ void k_packA(const float* __restrict__ in, unsigned* __restrict__ out) {
    int t = blockIdx.x * 256 + threadIdx.x;
    float2 v = reinterpret_cast<const float2*>(in)[t];
    out[t] = pk_h(v.x, v.y);
}

template<int N>
__global__ void k_packB(const float* __restrict__ in, unsigned* __restrict__ out) {
    int t = blockIdx.x * 256 + threadIdx.x;
    int kp = t / N, n = t - kp * N;
    out[t] = pk_h(in[(size_t)(2 * kp) * N + n], in[(size_t)(2 * kp + 1) * N + n]);
}

// ---------------- packed fp16 GEMM, cp.async double buffer, BM=128 BN=128 BK=32 ----------------
template<int NLD, int MODE>
__global__ void __launch_bounds__(256, 3)
k_gemm_hp(const unsigned* __restrict__ A, const unsigned* __restrict__ Bm, float* __restrict__ C) {
    __shared__ unsigned sAp[2][128 * 20];
    __shared__ unsigned sBp[2][16 * 132];

    int tid = threadIdx.x;
    int lane = tid & 31, wid = tid >> 5;
    int g = lane >> 2, t4 = lane & 3;
    int wm = wid & 3, wn = wid >> 2;
    int m0 = blockIdx.y * 128, n0 = blockIdx.x * 128;

    float acc[2][8][4];
    #pragma unroll
    for (int mt = 0; mt < 2; mt++)
        #pragma unroll
        for (int nt = 0; nt < 8; nt++)
            #pragma unroll
            for (int c = 0; c < 4; c++) acc[mt][nt][c] = 0.0f;

    int arow = tid >> 2, aseg = (tid & 3) * 4;
    int bkp = tid >> 5, bn4 = (tid & 31) * 4;

    #define ISSUE(ch, buf)                                                                  \
        do {                                                                                \
            int kk = (ch) * 16;                                                             \
            cp16(&sAp[buf][arow * 20 + aseg], A + (size_t)(m0 + arow) * 512 + kk + aseg);   \
            cp16(&sAp[buf][(arow + 64) * 20 + aseg],                                        \
                 A + (size_t)(m0 + arow + 64) * 512 + kk + aseg);                           \
            cp16(&sBp[buf][bkp * 132 + bn4], Bm + (size_t)(kk + bkp) * NLD + n0 + bn4);     \
            cp16(&sBp[buf][(bkp + 8) * 132 + bn4],                                          \
                 Bm + (size_t)(kk + bkp + 8) * NLD + n0 + bn4);                             \
        } while (0)

    ISSUE(0, 0); CP_COMMIT();
    ISSUE(1, 1); CP_COMMIT();

    for (int ch = 0; ch < 32; ch++) {
        CP_WAIT1();
        __syncthreads();
        int buf = ch & 1;

        #pragma unroll
        for (int s = 0; s < 2; s++) {
            int kb = s * 8;
            unsigned af[2][4];
            #pragma unroll
            for (int mt = 0; mt < 2; mt++) {
                int r = wm * 32 + mt * 16 + g;
                af[mt][0] = sAp[buf][r * 20 + kb + t4];
                af[mt][1] = sAp[buf][(r + 8) * 20 + kb + t4];
                af[mt][2] = sAp[buf][r * 20 + kb + t4 + 4];
                af[mt][3] = sAp[buf][(r + 8) * 20 + kb + t4 + 4];
            }
            #pragma unroll
            for (int nt = 0; nt < 8; nt++) {
                int n = wn * 64 + nt * 8 + g;
                unsigned b0 = sBp[buf][(kb + t4) * 132 + n];
                unsigned b1 = sBp[buf][(kb + t4 + 4) * 132 + n];
                #pragma unroll
                for (int mt = 0; mt < 2; mt++)
                    mma_f16(acc[mt][nt][0], acc[mt][nt][1], acc[mt][nt][2], acc[mt][nt][3],
                            af[mt][0], af[mt][1], af[mt][2], af[mt][3], b0, b1);
            }
        }
        __syncthreads();
        if (ch + 2 < 32) ISSUE(ch + 2, buf);
        CP_COMMIT();
    }
    #undef ISSUE

    #pragma unroll
    for (int mt = 0; mt < 2; mt++) {
        #pragma unroll
        for (int nt = 0; nt < 8; nt++) {
            int row = m0 + wm * 32 + mt * 16 + g;
            int col = n0 + wn * 64 + nt * 8 + t4 * 2;
            if (MODE == 0) {
                *reinterpret_cast<float2*>(C + (size_t)row * NLD + col) =
                    make_float2(acc[mt][nt][0], acc[mt][nt][1]);
                *reinterpret_cast<float2*>(C + (size_t)(row + 8) * NLD + col) =
                    make_float2(acc[mt][nt][2], acc[mt][nt][3]);
            } else {
                #pragma unroll
                for (int half = 0; half < 2; half++) {
                    int m = row + half * 8;
                    int b = m >> 10, l = m & 1023;
                    int s = col >> 10, rem = col & 1023;
                    int h = rem >> 6, d = rem & 63;
                    float* dst = (s == 0) ? g_q : (s == 1) ? g_k : g_v;
                    *reinterpret_cast<float2*>(dst + (size_t)((b * H_ + h) * L_ + l) * D_ + d) =
                        make_float2(acc[mt][nt][half * 2], acc[mt][nt][half * 2 + 1]);
                }
            }
        }
    }
}

// ---------------- kernel 2: RoPE -> packed fp16 q/k ----------------
__global__ void k_rope2() {
    int t = blockIdx.x * 256 + threadIdx.x;
    int bh = t >> 15;
    int rem = t & 32767;
    int l = rem >> 5;
    int j = rem & 31;
    float invf = expf(-(float)j * (logf(10000.0f) / 32.0f));
    float ang = (float)l * invf;
    float cs = cosf(ang), sn = sinf(ang);
    int base = (bh << 16) + (l << 6) + j;
    float q1 = g_q[base], q2 = g_q[base + 32];
    float qa = q1 * cs - q2 * sn;
    float qb = q2 * cs + q1 * sn;
    float k1 = g_k[base], k2 = g_k[base + 32];
    float ka = k1 * cs - k2 * sn;
    float kb = k2 * cs + k1 * sn;

    float qan = __shfl_down_sync(0xffffffffu, qa, 1);
    float qbn = __shfl_down_sync(0xffffffffu, qb, 1);
    float kan = __shfl_down_sync(0xffffffffu, ka, 1);
    float kbn = __shfl_down_sync(0xffffffffu, kb, 1);
    if ((j & 1) == 0) {
        int rowo = (bh << 10) + l;
        int p = j >> 1;
        g_qh[rowo * 32 + p]      = pk_h(qa, qan);
        g_qh[rowo * 32 + 16 + p] = pk_h(qb, qbn);
        g_kh[rowo * 32 + p]      = pk_h(ka, kan);
        g_kh[rowo * 32 + 16 + p] = pk_h(kb, kbn);
    }
}

// ---------------- kernel 2b: kerple table [dist][h] ----------------
__global__ void k_ktab(const float* __restrict__ log_p, const float* __restrict__ log_a) {
    int d = blockIdx.x * 256 + threadIdx.x;
    if (d >= L_) return;
    float dist = (float)d;
    #pragma unroll
    for (int h = 0; h < H_; h++) {
        float p = log1pf(expf(log_p[h]));
        float a = log1pf(expf(log_a[h]));
        g_kt[d * H_ + h] = -p * log1pf(a * dist);
    }
}

// ---------------- kernel 2c: transpose V -> g_vtp[bh][d][l/2] half2 ----------------
__global__ void __launch_bounds__(256) k_vt() {
    int lb = blockIdx.x;
    int bh = blockIdx.y;
    __shared__ float sT[128][65];
    int tid = threadIdx.x;
    const float* vb = g_v + ((size_t)bh * L_ + lb * 128) * D_;
    #pragma unroll
    for (int u = 0; u < 8; u++) {
        int id = u * 256 + tid;
        int l = id >> 4, c4 = (id & 15) * 4;
        float4 v = *reinterpret_cast<const float4*>(vb + l * D_ + c4);
        sT[l][c4] = v.x; sT[l][c4 + 1] = v.y; sT[l][c4 + 2] = v.z; sT[l][c4 + 3] = v.w;
    }
    __syncthreads();
    unsigned* out = g_vtp + (size_t)bh * D_ * (L_ / 2) + lb * 64;
    #pragma unroll
    for (int u = 0; u < 16; u++) {
        int id = u * 256 + tid;
        int d = id >> 6, lp = id & 63;
        out[(size_t)d * (L_ / 2) + lp] = pk_h(sT[2 * lp][d], sT[2 * lp + 1][d]);
    }
}

// ---------------- kernel 3: scores = q k^T * scale (fp16 mma, 128x128, single-shot D) ----------------
__global__ void __launch_bounds__(256) k_scores_h() {
    int jt = blockIdx.x, it = blockIdx.y, bh = blockIdx.z;
    if (jt > it) return;
    int i0 = it * 128, j0 = jt * 128;
    __shared__ unsigned sQp[128 * 33];
    __shared__ unsigned sKp[128 * 33];

    int tid = threadIdx.x;
    int lane = tid & 31, wid = tid >> 5;
    int g = lane >> 2, t4 = lane & 3;
    int wm = wid & 3, wn = wid >> 2;

    const unsigned* qb = g_qh + (size_t)(bh * L_ + i0) * 32;
    const unsigned* kb = g_kh + (size_t)(bh * L_ + j0) * 32;

    #pragma unroll
    for (int u = 0; u < 4; u++) {
        int id = u * 256 + tid;
        int row = id >> 3, seg = (id & 7) * 4;
        uint4 q = *reinterpret_cast<const uint4*>(qb + (size_t)row * 32 + seg);
        sQp[row * 33 + seg + 0] = q.x; sQp[row * 33 + seg + 1] = q.y;
        sQp[row * 33 + seg + 2] = q.z; sQp[row * 33 + seg + 3] = q.w;
        uint4 k = *reinterpret_cast<const uint4*>(kb + (size_t)row * 32 + seg);
        sKp[row * 33 + seg + 0] = k.x; sKp[row * 33 + seg + 1] = k.y;
        sKp[row * 33 + seg + 2] = k.z; sKp[row * 33 + seg + 3] = k.w;
    }
    __syncthreads();

    float acc[2][8][4];
    #pragma unroll
    for (int mt = 0; mt < 2; mt++)
        #pragma unroll
        for (int nt = 0; nt < 8; nt++)
            #pragma unroll
            for (int c = 0; c < 4; c++) acc[mt][nt][c] = 0.0f;

    #pragma unroll
    for (int s = 0; s < 4; s++) {
        int kb2 = s * 8;
        unsigned af[2][4];
        #pragma unroll
        for (int mt = 0; mt < 2; mt++) {
            int r = wm * 32 + mt * 16 + g;
            af[mt][0] = sQp[r * 33 + kb2 + t4];
            af[mt][1] = sQp[(r + 8) * 33 + kb2 + t4];
            af[mt][2] = sQp[r * 33 + kb2 + t4 + 4];
            af[mt][3] = sQp[(r + 8) * 33 + kb2 + t4 + 4];
        }
        #pragma unroll
        for (int nt = 0; nt < 8; nt++) {
            int n = wn * 64 + nt * 8 + g;
            unsigned b0 = sKp[n * 33 + kb2 + t4];
            unsigned b1 = sKp[n * 33 + kb2 + t4 + 4];
            #pragma unroll
            for (int mt = 0; mt < 2; mt++)
                mma_f16(acc[mt][nt][0], acc[mt][nt][1], acc[mt][nt][2], acc[mt][nt][3],
                        af[mt][0], af[mt][1], af[mt][2], af[mt][3], b0, b1);
        }
    }

    bool edge = (jt == it);
    #pragma unroll
    for (int mt = 0; mt < 2; mt++) {
        #pragma unroll
        for (int nt = 0; nt < 8; nt++) {
            #pragma unroll
            for (int half = 0; half < 2; half++) {
                int i = i0 + wm * 32 + mt * 16 + g + half * 8;
                int j = j0 + wn * 64 + nt * 8 + t4 * 2;
                float v0 = acc[mt][nt][half * 2] * 0.125f;
                float v1 = acc[mt][nt][half * 2 + 1] * 0.125f;
                if (edge) {
                    if (j > i) v0 = 0.0f;
                    if (j + 1 > i) v1 = 0.0f;
                }
                *reinterpret_cast<float2*>(g_s + (size_t)(bh * L_ + i) * L_ + j) =
                    make_float2(v0, v1);
            }
        }
    }
}

// ---------------- kernel 4: kerple + DAPE MLP (bf16 mma), 2 j-chunks per block ----------------
#define PC_ 18
__global__ void __launch_bounds__(256)
k_dape3(const float* __restrict__ w1, const float* __restrict__ b1,
        const float* __restrict__ w2, const float* __restrict__ b2) {
    int i = blockIdx.y;
    int b = blockIdx.z;
    int jbase = blockIdx.x * 256;
    if (jbase > i) return;

    __shared__ float sC[128 * 36];
    __shared__ unsigned sCb[128 * PC_];
    __shared__ unsigned sHb[128 * PC_];
    __shared__ unsigned w1p[16 * 33];
    __shared__ unsigned w2p[16 * 17];
    __shared__ float b1s[32], b2s[16];

    int tid = threadIdx.x;
    for (int t = tid; t < 512; t += 256) {
        int kp = t >> 5, n = t & 31;
        w1p[kp * 33 + n] = pk_bf16(w1[(2 * kp) * 32 + n], w1[(2 * kp + 1) * 32 + n]);
    }
    {
        int kp = tid >> 4, n = tid & 15;
        w2p[kp * 17 + n] = pk_bf16(w2[(2 * kp) * 16 + n], w2[(2 * kp + 1) * 16 + n]);
    }
    if (tid < 32) b1s[tid] = b1[tid];
    if (tid < 16) b2s[tid] = b2[tid];

    int lane = tid & 31, wid = tid >> 5;
    int g = lane >> 2, t4 = lane & 3;
    int r0 = wid * 16;
    __syncthreads();

    #pragma unroll
    for (int cc = 0; cc < 2; cc++) {
        int j0 = jbase + cc * 128;
        if (j0 > i) break;

        size_t off = (size_t)b * (H_ * L_ * L_) + (size_t)i * L_ + j0;
        if (tid < 128) {
            int r = tid;
            float c[16];
            #pragma unroll
            for (int h = 0; h < 16; h++) {
                c[h] = g_s[off + (size_t)h * (L_ * L_) + r];
                sC[r * 36 + h] = c[h];
            }
            #pragma unroll
            for (int p = 0; p < 8; p++)
                sCb[r * PC_ + p] = pk_bf16(c[2 * p], c[2 * p + 1]);
        } else {
            int r = tid - 128;
            int dist = i - (j0 + r);
            if (dist < 0) dist = 0;
            const float4* kt = reinterpret_cast<const float4*>(g_kt + dist * H_);
            float k[16];
            #pragma unroll
            for (int q = 0; q < 4; q++) {
                float4 v = kt[q];
                k[4 * q] = v.x; k[4 * q + 1] = v.y; k[4 * q + 2] = v.z; k[4 * q + 3] = v.w;
            }
            #pragma unroll
            for (int h = 0; h < 16; h++) sC[r * 36 + 16 + h] = k[h];
            #pragma unroll
            for (int p = 0; p < 8; p++)
                sCb[r * PC_ + 8 + p] = pk_bf16(k[2 * p], k[2 * p + 1]);
        }
        __syncthreads();

        float acc1[4][4];
        #pragma unroll
        for (int nt = 0; nt < 4; nt++)
            #pragma unroll
            for (int c = 0; c < 4; c++) acc1[nt][c] = 0.0f;
        #pragma unroll
        for (int ks = 0; ks < 2; ks++) {
            int kp = ks * 8;
            unsigned a0 = sCb[(r0 + g) * PC_ + kp + t4];
            unsigned a1 = sCb[(r0 + 8 + g) * PC_ + kp + t4];
            unsigned a2 = sCb[(r0 + g) * PC_ + kp + t4 + 4];
            unsigned a3 = sCb[(r0 + 8 + g) * PC_ + kp + t4 + 4];
            #pragma unroll
            for (int nt = 0; nt < 4; nt++) {
                int n = nt * 8 + g;
                unsigned b0 = w1p[(kp + t4) * 33 + n];
                unsigned b1f = w1p[(kp + t4 + 4) * 33 + n];
                mma_bf16(acc1[nt][0], acc1[nt][1], acc1[nt][2], acc1[nt][3],
                         a0, a1, a2, a3, b0, b1f);
            }
        }
        #pragma unroll
        for (int nt = 0; nt < 4; nt++)
            #pragma unroll
            for (int half = 0; half < 2; half++) {
                int row = r0 + g + half * 8;
                int col = nt * 8 + t4 * 2;
                float x0 = acc1[nt][half * 2 + 0] + b1s[col];
                float x1 = acc1[nt][half * 2 + 1] + b1s[col + 1];
                float g0 = 0.5f * x0 * (1.0f + erff(x0 * 0.70710678118f));
                float g1 = 0.5f * x1 * (1.0f + erff(x1 * 0.70710678118f));
                sHb[row * PC_ + nt * 4 + t4] = pk_bf16(g0, g1);
            }
        __syncwarp();

        float acc2[2][4];
        #pragma unroll
        for (int nt = 0; nt < 2; nt++)
            #pragma unroll
            for (int c = 0; c < 4; c++) acc2[nt][c] = 0.0f;
        #pragma unroll
        for (int ks = 0; ks < 2; ks++) {
            int kp = ks * 8;
            unsigned a0 = sHb[(r0 + g) * PC_ + kp + t4];
            unsigned a1 = sHb[(r0 + 8 + g) * PC_ + kp + t4];
            unsigned a2 = sHb[(r0 + g) * PC_ + kp + t4 + 4];
            unsigned a3 = sHb[(r0 + 8 + g) * PC_ + kp + t4 + 4];
            #pragma unroll
            for (int nt = 0; nt < 2; nt++) {
                int n = nt * 8 + g;
                unsigned b0 = w2p[(kp + t4) * 17 + n];
                unsigned b1f = w2p[(kp + t4 + 4) * 17 + n];
                mma_bf16(acc2[nt][0], acc2[nt][1], acc2[nt][2], acc2[nt][3],
                         a0, a1, a2, a3, b0, b1f);
            }
        }
        #pragma unroll
        for (int nt = 0; nt < 2; nt++)
            #pragma unroll
            for (int half = 0; half < 2; half++) {
                int row = r0 + g + half * 8;
                if (j0 + row <= i) {
                    #pragma unroll
                    for (int q = 0; q < 2; q++) {
                        int h = nt * 8 + t4 * 2 + q;
                        g_s[off + (size_t)h * (L_ * L_) + row] =
                            sC[row * 36 + h] + sC[row * 36 + 16 + h]
                            + acc2[nt][half * 2 + q] + b2s[h];
                    }
                }
            }
        __syncthreads();
    }
}

// ---------------- kernel 5: causal softmax per row -> fp16 weights in g_w ----------------
__global__ void k_softmax() {
    int row = blockIdx.x;
    int i = row & 1023;
    int n = i + 1;
    const float* S = g_s + (size_t)row * L_;
    __half* W = g_w + (size_t)row * L_;
    __shared__ float buf[1024];
    __shared__ float redm[4], reds[4];
    int tx = threadIdx.x;

    float m = -1e30f;
    for (int j2 = tx * 2; j2 < n; j2 += 256) {
        float2 v = *reinterpret_cast<const float2*>(S + j2);
        buf[j2] = v.x; m = fmaxf(m, v.x);
        if (j2 + 1 < n) { buf[j2 + 1] = v.y; m = fmaxf(m, v.y); }
    }
    #pragma unroll
    for (int o = 16; o; o >>= 1) m = fmaxf(m, __shfl_xor_sync(0xffffffffu, m, o));
    if ((tx & 31) == 0) redm[tx >> 5] = m;
    __syncthreads();
    m = fmaxf(fmaxf(redm[0], redm[1]), fmaxf(redm[2], redm[3]));

    float sum = 0.0f;
    for (int j2 = tx * 2; j2 < n; j2 += 256) {
        float e0 = expf(buf[j2] - m); buf[j2] = e0; sum += e0;
        if (j2 + 1 < n) { float e1 = expf(buf[j2 + 1] - m); buf[j2 + 1] = e1; sum += e1; }
    }
    #pragma unroll
    for (int o = 16; o; o >>= 1) sum += __shfl_xor_sync(0xffffffffu, sum, o);
    if ((tx & 31) == 0) reds[tx >> 5] = sum;
    __syncthreads();
    sum = reds[0] + reds[1] + reds[2] + reds[3];
    float inv = 1.0f / sum;
    for (int j2 = tx * 2; j2 < n; j2 += 256) {
        if (j2 + 1 < n)
            *reinterpret_cast<unsigned*>(W + j2) = pk_h(buf[j2] * inv, buf[j2 + 1] * inv);
        else
            W[j2] = __float2half_rn(buf[j2] * inv);
    }
}

// ---------------- kernel 6: out = weights @ v (fp16 mma, cp.async double buffer) ----------------
__global__ void __launch_bounds__(256) k_pv_h() {
    int it = gridDim.x - 1 - blockIdx.x;
    int bh = blockIdx.y;
    __shared__ unsigned sWp[2][128 * 20];
    __shared__ unsigned sVp[2][64 * 20];
    int i0 = it * 128;
    int tid = threadIdx.x;
    int lane = tid & 31, wid = tid >> 5;
    int g = lane >> 2, t4 = lane & 3;
    int wm = wid & 3, wn = wid >> 2;

    float acc[2][4][4];
    #pragma unroll
    for (int mt = 0; mt < 2; mt++)
        #pragma unroll
        for (int nt = 0; nt < 4; nt++)
            #pragma unroll
            for (int c = 0; c < 4; c++) acc[mt][nt][c] = 0.0f;

    const unsigned* wbase = reinterpret_cast<const unsigned*>(g_w) + (size_t)(bh * L_ + i0) * (L_ / 2);
    const unsigned* vbase = g_vtp + (size_t)bh * D_ * (L_ / 2);
    int nch = (it + 1) * 4;

    int wrow = tid >> 2, wseg = (tid & 3) * 4;   // W: 2 cp16/thread covering 128x16
    int vd = tid >> 2, vseg = (tid & 3) * 4;     // V: 1 cp16/thread covering 64x16

    #define ISSUE_PV(ch, buf)                                                                   \
        do {                                                                                    \
            int jp = (ch) * 16;                                                                 \
            cp16(&sWp[buf][wrow * 20 + wseg], wbase + (size_t)wrow * (L_ / 2) + jp + wseg);     \
            cp16(&sWp[buf][(wrow + 64) * 20 + wseg],                                            \
                 wbase + (size_t)(wrow + 64) * (L_ / 2) + jp + wseg);                           \
            if (tid < 256) { /* V: only 256 cp16 needed, one per thread */                      \
                cp16(&sVp[buf][vd * 20 + vseg], vbase + (size_t)vd * (L_ / 2) + jp + vseg);     \
            }                                                                                   \
        } while (0)

    ISSUE_PV(0, 0); CP_COMMIT();
    if (nch > 1) ISSUE_PV(1, 1);
    CP_COMMIT();

    for (int ch = 0; ch < nch; ch++) {
        CP_WAIT1();
        __syncthreads();
        int buf = ch & 1;

        #pragma unroll
        for (int s = 0; s < 2; s++) {
            int kb = s * 8;
            unsigned af[2][4];
            #pragma unroll
            for (int mt = 0; mt < 2; mt++) {
                int r = wm * 32 + mt * 16 + g;
                af[mt][0] = sWp[buf][r * 20 + kb + t4];
                af[mt][1] = sWp[buf][(r + 8) * 20 + kb + t4];
                af[mt][2] = sWp[buf][r * 20 + kb + t4 + 4];
                af[mt][3] = sWp[buf][(r + 8) * 20 + kb + t4 + 4];
            }
            #pragma unroll
            for (int nt = 0; nt < 4; nt++) {
                int n = wn * 32 + nt * 8 + g;
                unsigned b0 = sVp[buf][n * 20 + kb + t4];
                unsigned b1 = sVp[buf][n * 20 + kb + t4 + 4];
                #pragma unroll
                for (int mt = 0; mt < 2; mt++)
                    mma_f16(acc[mt][nt][0], acc[mt][nt][1], acc[mt][nt][2], acc[mt][nt][3],
                            af[mt][0], af[mt][1], af[mt][2], af[mt][3], b0, b1);
            }
        }
        __syncthreads();
        if (ch + 2 < nch) ISSUE_PV(ch + 2, buf);
        CP_COMMIT();
    }
    #undef ISSUE_PV

    int b = bh >> 4, h = bh & 15;
    #pragma unroll
    for (int mt = 0; mt < 2; mt++)
        #pragma unroll
        for (int nt = 0; nt < 4; nt++)
            #pragma unroll
            for (int half = 0; half < 2; half++) {
                int i = i0 + wm * 32 + mt * 16 + g + half * 8;
                int dp = wn * 16 + nt * 4 + t4;
                g_oh[(size_t)(b * L_ + i) * 512 + h * 32 + dp] =
                    pk_h(acc[mt][nt][half * 2], acc[mt][nt][half * 2 + 1]);
            }
}

// ---------------- launch ----------------
extern "C" void kernel_launch(void* const* d_in, const int* in_sizes, int n_in,
                              void* d_out, int out_size) {
    const float* x     = (const float*)d_in[0];
    const float* w_qkv = (const float*)d_in[1];
    const float* w_o   = (const float*)d_in[2];
    const float* log_p = (const float*)d_in[3];
    const float* log_a = (const float*)d_in[4];
    const float* w1    = (const float*)d_in[5];
    const float* b1    = (const float*)d_in[6];
    const float* w2    = (const float*)d_in[7];
    const float* b2    = (const float*)d_in[8];
    float* y = (float*)d_out;

    void* xh_ptr = nullptr;  cudaGetSymbolAddress(&xh_ptr, g_xh);
    void* wq_ptr = nullptr;  cudaGetSymbolAddress(&wq_ptr, g_wqkvh);
    void* wo_ptr = nullptr;  cudaGetSymbolAddress(&wo_ptr, g_woh);
    void* oh_ptr = nullptr;  cudaGetSymbolAddress(&oh_ptr, g_oh);

    // 0. pack inputs to fp16
    k_packA<<<(M_ * HID_ / 2) / 256, 256>>>(x, (unsigned*)xh_ptr);
    k_packB<N3_><<<(HID_ / 2) * N3_ / 256, 256>>>(w_qkv, (unsigned*)wq_ptr);
    k_packB<HID_><<<(HID_ / 2) * HID_ / 256, 256>>>(w_o, (unsigned*)wo_ptr);

    // 1. QKV projection (packed fp16 mma, cp.async, 3 blocks/SM)
    k_gemm_hp<N3_, 1><<<dim3(N3_ / 128, M_ / 128), 256>>>((const unsigned*)xh_ptr, (const unsigned*)wq_ptr, nullptr);
    // 2. RoPE -> packed fp16 q/k; kerple table; V transpose
    k_rope2<<<(B_ * H_ * L_ * 32) / 256, 256>>>();
    k_ktab<<<4, 256>>>(log_p, log_a);
    k_vt<<<dim3(8, B_ * H_), 256>>>();
    // 3. scores (fp16 mma)
    k_scores_h<<<dim3(8, 8, B_ * H_), 256>>>();
    // 4. kerple + DAPE MLP
    k_dape3<<<dim3(4, L_, B_), 256>>>(w1, b1, w2, b2);
    // 5. softmax -> fp16 weights
    k_softmax<<<B_ * H_ * L_, 128>>>();
    // 6. PV (cp.async double buffer) -> packed fp16 g_oh
    k_pv_h<<<dim3(8, B_ * H_), 256>>>();
    // 7. output projection (packed fp16 mma, cp.async) -> y fp32
    k_gemm_hp<HID_, 0><<<dim3(HID_ / 128, M_ / 128), 256>>>((const unsigned*)oh_ptr, (const unsigned*)wo_ptr, y);
}

// round 17
// speedup vs baseline: 1.6778x; 1.0012x over previous
#include <cuda_runtime.h>
#include <cuda_fp16.h>
#include <math.h>

#define B_  2
#define L_  1024
#define H_  16
#define D_  64
#define HID_ 1024
#define N3_ 3072
#define HD_ 1024   // H*D
#define M_  2048   // B*L

// ---------------- scratch (device globals; no allocations) ----------------
__device__ float g_q[B_ * H_ * L_ * D_];
__device__ float g_k[B_ * H_ * L_ * D_];
__device__ float g_v[B_ * H_ * L_ * D_];
__device__ unsigned g_qh[B_ * H_ * L_ * (D_ / 2)];
__device__ unsigned g_kh[B_ * H_ * L_ * (D_ / 2)];
__device__ float g_s[B_ * H_ * L_ * L_];
__device__ __half g_w[B_ * H_ * L_ * L_];
__device__ unsigned g_vtp[B_ * H_ * D_ * (L_ / 2)];
__device__ unsigned g_oh[M_ * (HD_ / 2)];
__device__ float g_kt[L_ * H_];
__device__ unsigned g_xh[M_ * (HID_ / 2)];
__device__ unsigned g_wqkvh[(HID_ / 2) * N3_];
__device__ unsigned g_woh[(HID_ / 2) * HID_];

// ---------------- helpers ----------------
__device__ __forceinline__ unsigned pk_bf16(float lo, float hi) {
    unsigned r;
    asm("cvt.rn.bf16x2.f32 %0, %1, %2;" : "=r"(r) : "f"(hi), "f"(lo));
    return r;
}

__device__ __forceinline__ unsigned pk_h(float lo, float hi) {
    unsigned r;
    asm("cvt.rn.f16x2.f32 %0, %1, %2;" : "=r"(r) : "f"(hi), "f"(lo));
    return r;
}

__device__ __forceinline__ void mma_bf16(float& d0, float& d1, float& d2, float& d3,
                                         unsigned a0, unsigned a1, unsigned a2, unsigned a3,
                                         unsigned b0, unsigned b1) {
    asm volatile(
        "mma.sync.aligned.m16n8k16.row.col.f32.bf16.bf16.f32 "
        "{%0,%1,%2,%3}, {%4,%5,%6,%7}, {%8,%9}, {%0,%1,%2,%3};"
        : "+f"(d0), "+f"(d1), "+f"(d2), "+f"(d3)
        : "r"(a0), "r"(a1), "r"(a2), "r"(a3), "r"(b0), "r"(b1));
}

__device__ __forceinline__ void mma_f16(float& d0, float& d1, float& d2, float& d3,
                                        unsigned a0, unsigned a1, unsigned a2, unsigned a3,
                                        unsigned b0, unsigned b1) {
    asm volatile(
        "mma.sync.aligned.m16n8k16.row.col.f32.f16.f16.f32 "
        "{%0,%1,%2,%3}, {%4,%5,%6,%7}, {%8,%9}, {%0,%1,%2,%3};"
        : "+f"(d0), "+f"(d1), "+f"(d2), "+f"(d3)
        : "r"(a0), "r"(a1), "r"(a2), "r"(a3), "r"(b0), "r"(b1));
}

__device__ __forceinline__ void cp16(unsigned* smem, const unsigned* gmem) {
    unsigned saddr = (unsigned)__cvta_generic_to_shared(smem);
    asm volatile("cp.async.cg.shared.global [%0], [%1], 16;\n" :: "r"(saddr), "l"(gmem));
}
#define CP_COMMIT() asm volatile("cp.async.commit_group;\n" ::: "memory")
#define CP_WAIT1()  asm volatile("cp.async.wait_group 1;\n" ::: "memory")

__device__ __forceinline__ float gelu_t(float x) {
    float x3 = x * x * x;
    return 0.5f * x * (1.0f + tanhf(0.7978845608f * (x + 0.044715f * x3)));
}

// ---------------- pack kernels ----------------
__global__ void k_packA(const float* __restrict__ in, unsigned* __restrict__ out) {
    int t = blockIdx.x * 256 + threadIdx.x;
    float2 v = reinterpret_cast<const float2*>(in)[t];
    out[t] = pk_h(v.x, v.y);
}

template<int N>
__global__ void k_packB(const float* __restrict__ in, unsigned* __restrict__ out) {
    int t = blockIdx.x * 256 + threadIdx.x;
    int kp = t / N, n = t - kp * N;
    out[t] = pk_h(in[(size_t)(2 * kp) * N + n], in[(size_t)(2 * kp + 1) * N + n]);
}

// ---------------- packed fp16 GEMM, cp.async double buffer, BM=128 BN=128 BK=32 ----------------
template<int NLD, int MODE>
__global__ void __launch_bounds__(256)
k_gemm_hp(const unsigned* __restrict__ A, const unsigned* __restrict__ Bm, float* __restrict__ C) {
    __shared__ unsigned sAp[2][128 * 20];
    __shared__ unsigned sBp[2][16 * 132];

    int tid = threadIdx.x;
    int lane = tid & 31, wid = tid >> 5;
    int g = lane >> 2, t4 = lane & 3;
    int wm = wid & 3, wn = wid >> 2;
    int m0 = blockIdx.y * 128, n0 = blockIdx.x * 128;

    float acc[2][8][4];
    #pragma unroll
    for (int mt = 0; mt < 2; mt++)
        #pragma unroll
        for (int nt = 0; nt < 8; nt++)
            #pragma unroll
            for (int c = 0; c < 4; c++) acc[mt][nt][c] = 0.0f;

    int arow = tid >> 2, aseg = (tid & 3) * 4;
    int bkp = tid >> 5, bn4 = (tid & 31) * 4;

    #define ISSUE(ch, buf)                                                                  \
        do {                                                                                \
            int kk = (ch) * 16;                                                             \
            cp16(&sAp[buf][arow * 20 + aseg], A + (size_t)(m0 + arow) * 512 + kk + aseg);   \
            cp16(&sAp[buf][(arow + 64) * 20 + aseg],                                        \
                 A + (size_t)(m0 + arow + 64) * 512 + kk + aseg);                           \
            cp16(&sBp[buf][bkp * 132 + bn4], Bm + (size_t)(kk + bkp) * NLD + n0 + bn4);     \
            cp16(&sBp[buf][(bkp + 8) * 132 + bn4],                                          \
                 Bm + (size_t)(kk + bkp + 8) * NLD + n0 + bn4);                             \
        } while (0)

    ISSUE(0, 0); CP_COMMIT();
    ISSUE(1, 1); CP_COMMIT();

    for (int ch = 0; ch < 32; ch++) {
        CP_WAIT1();
        __syncthreads();
        int buf = ch & 1;

        #pragma unroll
        for (int s = 0; s < 2; s++) {
            int kb = s * 8;
            unsigned af[2][4];
            #pragma unroll
            for (int mt = 0; mt < 2; mt++) {
                int r = wm * 32 + mt * 16 + g;
                af[mt][0] = sAp[buf][r * 20 + kb + t4];
                af[mt][1] = sAp[buf][(r + 8) * 20 + kb + t4];
                af[mt][2] = sAp[buf][r * 20 + kb + t4 + 4];
                af[mt][3] = sAp[buf][(r + 8) * 20 + kb + t4 + 4];
            }
            #pragma unroll
            for (int nt = 0; nt < 8; nt++) {
                int n = wn * 64 + nt * 8 + g;
                unsigned b0 = sBp[buf][(kb + t4) * 132 + n];
                unsigned b1 = sBp[buf][(kb + t4 + 4) * 132 + n];
                #pragma unroll
                for (int mt = 0; mt < 2; mt++)
                    mma_f16(acc[mt][nt][0], acc[mt][nt][1], acc[mt][nt][2], acc[mt][nt][3],
                            af[mt][0], af[mt][1], af[mt][2], af[mt][3], b0, b1);
            }
        }
        __syncthreads();
        if (ch + 2 < 32) ISSUE(ch + 2, buf);
        CP_COMMIT();
    }
    #undef ISSUE

    #pragma unroll
    for (int mt = 0; mt < 2; mt++) {
        #pragma unroll
        for (int nt = 0; nt < 8; nt++) {
            int row = m0 + wm * 32 + mt * 16 + g;
            int col = n0 + wn * 64 + nt * 8 + t4 * 2;
            if (MODE == 0) {
                *reinterpret_cast<float2*>(C + (size_t)row * NLD + col) =
                    make_float2(acc[mt][nt][0], acc[mt][nt][1]);
                *reinterpret_cast<float2*>(C + (size_t)(row + 8) * NLD + col) =
                    make_float2(acc[mt][nt][2], acc[mt][nt][3]);
            } else {
                #pragma unroll
                for (int half = 0; half < 2; half++) {
                    int m = row + half * 8;
                    int b = m >> 10, l = m & 1023;
                    int s = col >> 10, rem = col & 1023;
                    int h = rem >> 6, d = rem & 63;
                    float* dst = (s == 0) ? g_q : (s == 1) ? g_k : g_v;
                    *reinterpret_cast<float2*>(dst + (size_t)((b * H_ + h) * L_ + l) * D_ + d) =
                        make_float2(acc[mt][nt][half * 2], acc[mt][nt][half * 2 + 1]);
                }
            }
        }
    }
}

// ---------------- kernel 2: RoPE -> packed fp16 q/k ----------------
__global__ void k_rope2() {
    int t = blockIdx.x * 256 + threadIdx.x;
    int bh = t >> 15;
    int rem = t & 32767;
    int l = rem >> 5;
    int j = rem & 31;
    float invf = expf(-(float)j * (logf(10000.0f) / 32.0f));
    float ang = (float)l * invf;
    float cs = cosf(ang), sn = sinf(ang);
    int base = (bh << 16) + (l << 6) + j;
    float q1 = g_q[base], q2 = g_q[base + 32];
    float qa = q1 * cs - q2 * sn;
    float qb = q2 * cs + q1 * sn;
    float k1 = g_k[base], k2 = g_k[base + 32];
    float ka = k1 * cs - k2 * sn;
    float kb = k2 * cs + k1 * sn;

    float qan = __shfl_down_sync(0xffffffffu, qa, 1);
    float qbn = __shfl_down_sync(0xffffffffu, qb, 1);
    float kan = __shfl_down_sync(0xffffffffu, ka, 1);
    float kbn = __shfl_down_sync(0xffffffffu, kb, 1);
    if ((j & 1) == 0) {
        int rowo = (bh << 10) + l;
        int p = j >> 1;
        g_qh[rowo * 32 + p]      = pk_h(qa, qan);
        g_qh[rowo * 32 + 16 + p] = pk_h(qb, qbn);
        g_kh[rowo * 32 + p]      = pk_h(ka, kan);
        g_kh[rowo * 32 + 16 + p] = pk_h(kb, kbn);
    }
}

// ---------------- kernel 2b: kerple table [dist][h] ----------------
__global__ void k_ktab(const float* __restrict__ log_p, const float* __restrict__ log_a) {
    int d = blockIdx.x * 256 + threadIdx.x;
    if (d >= L_) return;
    float dist = (float)d;
    #pragma unroll
    for (int h = 0; h < H_; h++) {
        float p = log1pf(expf(log_p[h]));
        float a = log1pf(expf(log_a[h]));
        g_kt[d * H_ + h] = -p * log1pf(a * dist);
    }
}

// ---------------- kernel 2c: transpose V -> g_vtp[bh][d][l/2] half2 ----------------
__global__ void __launch_bounds__(256) k_vt() {
    int lb = blockIdx.x;
    int bh = blockIdx.y;
    __shared__ float sT[128][65];
    int tid = threadIdx.x;
    const float* vb = g_v + ((size_t)bh * L_ + lb * 128) * D_;
    #pragma unroll
    for (int u = 0; u < 8; u++) {
        int id = u * 256 + tid;
        int l = id >> 4, c4 = (id & 15) * 4;
        float4 v = *reinterpret_cast<const float4*>(vb + l * D_ + c4);
        sT[l][c4] = v.x; sT[l][c4 + 1] = v.y; sT[l][c4 + 2] = v.z; sT[l][c4 + 3] = v.w;
    }
    __syncthreads();
    unsigned* out = g_vtp + (size_t)bh * D_ * (L_ / 2) + lb * 64;
    #pragma unroll
    for (int u = 0; u < 16; u++) {
        int id = u * 256 + tid;
        int d = id >> 6, lp = id & 63;
        out[(size_t)d * (L_ / 2) + lp] = pk_h(sT[2 * lp][d], sT[2 * lp + 1][d]);
    }
}

// ---------------- kernel 3: scores = q k^T * scale (fp16 mma, 128x128) ----------------
__global__ void __launch_bounds__(256) k_scores_h() {
    int jt = blockIdx.x, it = blockIdx.y, bh = blockIdx.z;
    if (jt > it) return;
    int i0 = it * 128, j0 = jt * 128;
    __shared__ unsigned sQp[128 * 33];
    __shared__ unsigned sKp[128 * 33];

    int tid = threadIdx.x;
    int lane = tid & 31, wid = tid >> 5;
    int g = lane >> 2, t4 = lane & 3;
    int wm = wid & 3, wn = wid >> 2;

    const unsigned* qb = g_qh + (size_t)(bh * L_ + i0) * 32;
    const unsigned* kb = g_kh + (size_t)(bh * L_ + j0) * 32;

    #pragma unroll
    for (int u = 0; u < 4; u++) {
        int id = u * 256 + tid;
        int row = id >> 3, seg = (id & 7) * 4;
        uint4 q = *reinterpret_cast<const uint4*>(qb + (size_t)row * 32 + seg);
        sQp[row * 33 + seg + 0] = q.x; sQp[row * 33 + seg + 1] = q.y;
        sQp[row * 33 + seg + 2] = q.z; sQp[row * 33 + seg + 3] = q.w;
        uint4 k = *reinterpret_cast<const uint4*>(kb + (size_t)row * 32 + seg);
        sKp[row * 33 + seg + 0] = k.x; sKp[row * 33 + seg + 1] = k.y;
        sKp[row * 33 + seg + 2] = k.z; sKp[row * 33 + seg + 3] = k.w;
    }
    __syncthreads();

    float acc[2][8][4];
    #pragma unroll
    for (int mt = 0; mt < 2; mt++)
        #pragma unroll
        for (int nt = 0; nt < 8; nt++)
            #pragma unroll
            for (int c = 0; c < 4; c++) acc[mt][nt][c] = 0.0f;

    #pragma unroll
    for (int s = 0; s < 4; s++) {
        int kb2 = s * 8;
        unsigned af[2][4];
        #pragma unroll
        for (int mt = 0; mt < 2; mt++) {
            int r = wm * 32 + mt * 16 + g;
            af[mt][0] = sQp[r * 33 + kb2 + t4];
            af[mt][1] = sQp[(r + 8) * 33 + kb2 + t4];
            af[mt][2] = sQp[r * 33 + kb2 + t4 + 4];
            af[mt][3] = sQp[(r + 8) * 33 + kb2 + t4 + 4];
        }
        #pragma unroll
        for (int nt = 0; nt < 8; nt++) {
            int n = wn * 64 + nt * 8 + g;
            unsigned b0 = sKp[n * 33 + kb2 + t4];
            unsigned b1 = sKp[n * 33 + kb2 + t4 + 4];
            #pragma unroll
            for (int mt = 0; mt < 2; mt++)
                mma_f16(acc[mt][nt][0], acc[mt][nt][1], acc[mt][nt][2], acc[mt][nt][3],
                        af[mt][0], af[mt][1], af[mt][2], af[mt][3], b0, b1);
        }
    }

    bool edge = (jt == it);
    #pragma unroll
    for (int mt = 0; mt < 2; mt++) {
        #pragma unroll
        for (int nt = 0; nt < 8; nt++) {
            #pragma unroll
            for (int half = 0; half < 2; half++) {
                int i = i0 + wm * 32 + mt * 16 + g + half * 8;
                int j = j0 + wn * 64 + nt * 8 + t4 * 2;
                float v0 = acc[mt][nt][half * 2] * 0.125f;
                float v1 = acc[mt][nt][half * 2 + 1] * 0.125f;
                if (edge) {
                    if (j > i) v0 = 0.0f;
                    if (j + 1 > i) v1 = 0.0f;
                }
                *reinterpret_cast<float2*>(g_s + (size_t)(bh * L_ + i) * L_ + j) =
                    make_float2(v0, v1);
            }
        }
    }
}

// ---------------- kernel 4: kerple + DAPE MLP (bf16 mma), 2 j-chunks per block ----------------
#define PC_ 18
__global__ void __launch_bounds__(256)
k_dape3(const float* __restrict__ w1, const float* __restrict__ b1,
        const float* __restrict__ w2, const float* __restrict__ b2) {
    int i = blockIdx.y;
    int b = blockIdx.z;
    int jbase = blockIdx.x * 256;
    if (jbase > i) return;

    __shared__ float sC[128 * 36];
    __shared__ unsigned sCb[128 * PC_];
    __shared__ unsigned sHb[128 * PC_];
    __shared__ unsigned w1p[16 * 33];
    __shared__ unsigned w2p[16 * 17];
    __shared__ float b1s[32], b2s[16];

    int tid = threadIdx.x;
    for (int t = tid; t < 512; t += 256) {
        int kp = t >> 5, n = t & 31;
        w1p[kp * 33 + n] = pk_bf16(w1[(2 * kp) * 32 + n], w1[(2 * kp + 1) * 32 + n]);
    }
    {
        int kp = tid >> 4, n = tid & 15;
        w2p[kp * 17 + n] = pk_bf16(w2[(2 * kp) * 16 + n], w2[(2 * kp + 1) * 16 + n]);
    }
    if (tid < 32) b1s[tid] = b1[tid];
    if (tid < 16) b2s[tid] = b2[tid];

    int lane = tid & 31, wid = tid >> 5;
    int g = lane >> 2, t4 = lane & 3;
    int r0 = wid * 16;
    __syncthreads();

    #pragma unroll
    for (int cc = 0; cc < 2; cc++) {
        int j0 = jbase + cc * 128;
        if (j0 > i) break;

        size_t off = (size_t)b * (H_ * L_ * L_) + (size_t)i * L_ + j0;
        if (tid < 128) {
            int r = tid;
            float c[16];
            #pragma unroll
            for (int h = 0; h < 16; h++) {
                c[h] = g_s[off + (size_t)h * (L_ * L_) + r];
                sC[r * 36 + h] = c[h];
            }
            #pragma unroll
            for (int p = 0; p < 8; p++)
                sCb[r * PC_ + p] = pk_bf16(c[2 * p], c[2 * p + 1]);
        } else {
            int r = tid - 128;
            int dist = i - (j0 + r);
            if (dist < 0) dist = 0;
            const float4* kt = reinterpret_cast<const float4*>(g_kt + dist * H_);
            float k[16];
            #pragma unroll
            for (int q = 0; q < 4; q++) {
                float4 v = kt[q];
                k[4 * q] = v.x; k[4 * q + 1] = v.y; k[4 * q + 2] = v.z; k[4 * q + 3] = v.w;
            }
            #pragma unroll
            for (int h = 0; h < 16; h++) sC[r * 36 + 16 + h] = k[h];
            #pragma unroll
            for (int p = 0; p < 8; p++)
                sCb[r * PC_ + 8 + p] = pk_bf16(k[2 * p], k[2 * p + 1]);
        }
        __syncthreads();

        float acc1[4][4];
        #pragma unroll
        for (int nt = 0; nt < 4; nt++)
            #pragma unroll
            for (int c = 0; c < 4; c++) acc1[nt][c] = 0.0f;
        #pragma unroll
        for (int ks = 0; ks < 2; ks++) {
            int kp = ks * 8;
            unsigned a0 = sCb[(r0 + g) * PC_ + kp + t4];
            unsigned a1 = sCb[(r0 + 8 + g) * PC_ + kp + t4];
            unsigned a2 = sCb[(r0 + g) * PC_ + kp + t4 + 4];
            unsigned a3 = sCb[(r0 + 8 + g) * PC_ + kp + t4 + 4];
            #pragma unroll
            for (int nt = 0; nt < 4; nt++) {
                int n = nt * 8 + g;
                unsigned b0 = w1p[(kp + t4) * 33 + n];
                unsigned b1f = w1p[(kp + t4 + 4) * 33 + n];
                mma_bf16(acc1[nt][0], acc1[nt][1], acc1[nt][2], acc1[nt][3],
                         a0, a1, a2, a3, b0, b1f);
            }
        }
        #pragma unroll
        for (int nt = 0; nt < 4; nt++)
            #pragma unroll
            for (int half = 0; half < 2; half++) {
                int row = r0 + g + half * 8;
                int col = nt * 8 + t4 * 2;
                float x0 = acc1[nt][half * 2 + 0] + b1s[col];
                float x1 = acc1[nt][half * 2 + 1] + b1s[col + 1];
                sHb[row * PC_ + nt * 4 + t4] = pk_bf16(gelu_t(x0), gelu_t(x1));
            }
        __syncwarp();

        float acc2[2][4];
        #pragma unroll
        for (int nt = 0; nt < 2; nt++)
            #pragma unroll
            for (int c = 0; c < 4; c++) acc2[nt][c] = 0.0f;
        #pragma unroll
        for (int ks = 0; ks < 2; ks++) {
            int kp = ks * 8;
            unsigned a0 = sHb[(r0 + g) * PC_ + kp + t4];
            unsigned a1 = sHb[(r0 + 8 + g) * PC_ + kp + t4];
            unsigned a2 = sHb[(r0 + g) * PC_ + kp + t4 + 4];
            unsigned a3 = sHb[(r0 + 8 + g) * PC_ + kp + t4 + 4];
            #pragma unroll
            for (int nt = 0; nt < 2; nt++) {
                int n = nt * 8 + g;
                unsigned b0 = w2p[(kp + t4) * 17 + n];
                unsigned b1f = w2p[(kp + t4 + 4) * 17 + n];
                mma_bf16(acc2[nt][0], acc2[nt][1], acc2[nt][2], acc2[nt][3],
                         a0, a1, a2, a3, b0, b1f);
            }
        }
        #pragma unroll
        for (int nt = 0; nt < 2; nt++)
            #pragma unroll
            for (int half = 0; half < 2; half++) {
                int row = r0 + g + half * 8;
                if (j0 + row <= i) {
                    #pragma unroll
                    for (int q = 0; q < 2; q++) {
                        int h = nt * 8 + t4 * 2 + q;
                        g_s[off + (size_t)h * (L_ * L_) + row] =
                            sC[row * 36 + h] + sC[row * 36 + 16 + h]
                            + acc2[nt][half * 2 + q] + b2s[h];
                    }
                }
            }
        __syncthreads();
    }
}

// ---------------- kernel 5: causal softmax per row -> fp16 weights (float4) ----------------
__global__ void k_softmax() {
    int row = blockIdx.x;
    int i = row & 1023;
    int n = i + 1;
    const float* S = g_s + (size_t)row * L_;
    __half* W = g_w + (size_t)row * L_;
    __shared__ float buf[1024];
    __shared__ float redm[4], reds[4];
    int tx = threadIdx.x;

    float m = -1e30f;
    for (int j4 = tx * 4; j4 < n; j4 += 512) {
        float4 v = *reinterpret_cast<const float4*>(S + j4);
        buf[j4] = v.x; m = fmaxf(m, v.x);
        if (j4 + 1 < n) { buf[j4 + 1] = v.y; m = fmaxf(m, v.y); }
        if (j4 + 2 < n) { buf[j4 + 2] = v.z; m = fmaxf(m, v.z); }
        if (j4 + 3 < n) { buf[j4 + 3] = v.w; m = fmaxf(m, v.w); }
    }
    #pragma unroll
    for (int o = 16; o; o >>= 1) m = fmaxf(m, __shfl_xor_sync(0xffffffffu, m, o));
    if ((tx & 31) == 0) redm[tx >> 5] = m;
    __syncthreads();
    m = fmaxf(fmaxf(redm[0], redm[1]), fmaxf(redm[2], redm[3]));

    float sum = 0.0f;
    for (int j4 = tx * 4; j4 < n; j4 += 512) {
        float e0 = expf(buf[j4] - m); buf[j4] = e0; sum += e0;
        if (j4 + 1 < n) { float e = expf(buf[j4 + 1] - m); buf[j4 + 1] = e; sum += e; }
        if (j4 + 2 < n) { float e = expf(buf[j4 + 2] - m); buf[j4 + 2] = e; sum += e; }
        if (j4 + 3 < n) { float e = expf(buf[j4 + 3] - m); buf[j4 + 3] = e; sum += e; }
    }
    #pragma unroll
    for (int o = 16; o; o >>= 1) sum += __shfl_xor_sync(0xffffffffu, sum, o);
    if ((tx & 31) == 0) reds[tx >> 5] = sum;
    __syncthreads();
    sum = reds[0] + reds[1] + reds[2] + reds[3];
    float inv = 1.0f / sum;
    for (int j4 = tx * 4; j4 < n; j4 += 512) {
        if (j4 + 3 < n) {
            uint2 pk;
            pk.x = pk_h(buf[j4] * inv, buf[j4 + 1] * inv);
            pk.y = pk_h(buf[j4 + 2] * inv, buf[j4 + 3] * inv);
            *reinterpret_cast<uint2*>(W + j4) = pk;
        } else {
            W[j4] = __float2half_rn(buf[j4] * inv);
            if (j4 + 1 < n) W[j4 + 1] = __float2half_rn(buf[j4 + 1] * inv);
            if (j4 + 2 < n) W[j4 + 2] = __float2half_rn(buf[j4 + 2] * inv);
        }
    }
}

// ---------------- kernel 6: out = weights @ v (fp16 mma, cp.async double buffer) ----------------
__global__ void __launch_bounds__(256) k_pv_h() {
    int it = gridDim.x - 1 - blockIdx.x;
    int bh = blockIdx.y;
    __shared__ unsigned sWp[2][128 * 20];
    __shared__ unsigned sVp[2][64 * 20];
    int i0 = it * 128;
    int tid = threadIdx.x;
    int lane = tid & 31, wid = tid >> 5;
    int g = lane >> 2, t4 = lane & 3;
    int wm = wid & 3, wn = wid >> 2;

    float acc[2][4][4];
    #pragma unroll
    for (int mt = 0; mt < 2; mt++)
        #pragma unroll
        for (int nt = 0; nt < 4; nt++)
            #pragma unroll
            for (int c = 0; c < 4; c++) acc[mt][nt][c] = 0.0f;

    const unsigned* wbase = reinterpret_cast<const unsigned*>(g_w) + (size_t)(bh * L_ + i0) * (L_ / 2);
    const unsigned* vbase = g_vtp + (size_t)bh * D_ * (L_ / 2);
    int nch = (it + 1) * 4;

    int wrow = tid >> 2, wseg = (tid & 3) * 4;
    int vd = tid >> 2, vseg = (tid & 3) * 4;

    #define ISSUE_PV(ch, buf)                                                                   \
        do {                                                                                    \
            int jp = (ch) * 16;                                                                 \
            cp16(&sWp[buf][wrow * 20 + wseg], wbase + (size_t)wrow * (L_ / 2) + jp + wseg);     \
            cp16(&sWp[buf][(wrow + 64) * 20 + wseg],                                            \
                 wbase + (size_t)(wrow + 64) * (L_ / 2) + jp + wseg);                           \
            cp16(&sVp[buf][vd * 20 + vseg], vbase + (size_t)vd * (L_ / 2) + jp + vseg);         \
        } while (0)

    ISSUE_PV(0, 0); CP_COMMIT();
    if (nch > 1) ISSUE_PV(1, 1);
    CP_COMMIT();

    for (int ch = 0; ch < nch; ch++) {
        CP_WAIT1();
        __syncthreads();
        int buf = ch & 1;

        #pragma unroll
        for (int s = 0; s < 2; s++) {
            int kb = s * 8;
            unsigned af[2][4];
            #pragma unroll
            for (int mt = 0; mt < 2; mt++) {
                int r = wm * 32 + mt * 16 + g;
                af[mt][0] = sWp[buf][r * 20 + kb + t4];
                af[mt][1] = sWp[buf][(r + 8) * 20 + kb + t4];
                af[mt][2] = sWp[buf][r * 20 + kb + t4 + 4];
                af[mt][3] = sWp[buf][(r + 8) * 20 + kb + t4 + 4];
            }
            #pragma unroll
            for (int nt = 0; nt < 4; nt++) {
                int n = wn * 32 + nt * 8 + g;
                unsigned b0 = sVp[buf][n * 20 + kb + t4];
                unsigned b1 = sVp[buf][n * 20 + kb + t4 + 4];
                #pragma unroll
                for (int mt = 0; mt < 2; mt++)
                    mma_f16(acc[mt][nt][0], acc[mt][nt][1], acc[mt][nt][2], acc[mt][nt][3],
                            af[mt][0], af[mt][1], af[mt][2], af[mt][3], b0, b1);
            }
        }
        __syncthreads();
        if (ch + 2 < nch) ISSUE_PV(ch + 2, buf);
        CP_COMMIT();
    }
    #undef ISSUE_PV

    int b = bh >> 4, h = bh & 15;
    #pragma unroll
    for (int mt = 0; mt < 2; mt++)
        #pragma unroll
        for (int nt = 0; nt < 4; nt++)
            #pragma unroll
            for (int half = 0; half < 2; half++) {
                int i = i0 + wm * 32 + mt * 16 + g + half * 8;
                int dp = wn * 16 + nt * 4 + t4;
                g_oh[(size_t)(b * L_ + i) * 512 + h * 32 + dp] =
                    pk_h(acc[mt][nt][half * 2], acc[mt][nt][half * 2 + 1]);
            }
}

// ---------------- launch ----------------
extern "C" void kernel_launch(void* const* d_in, const int* in_sizes, int n_in,
                              void* d_out, int out_size) {
    const float* x     = (const float*)d_in[0];
    const float* w_qkv = (const float*)d_in[1];
    const float* w_o   = (const float*)d_in[2];
    const float* log_p = (const float*)d_in[3];
    const float* log_a = (const float*)d_in[4];
    const float* w1    = (const float*)d_in[5];
    const float* b1    = (const float*)d_in[6];
    const float* w2    = (const float*)d_in[7];
    const float* b2    = (const float*)d_in[8];
    float* y = (float*)d_out;

    void* xh_ptr = nullptr;  cudaGetSymbolAddress(&xh_ptr, g_xh);
    void* wq_ptr = nullptr;  cudaGetSymbolAddress(&wq_ptr, g_wqkvh);
    void* wo_ptr = nullptr;  cudaGetSymbolAddress(&wo_ptr, g_woh);
    void* oh_ptr = nullptr;  cudaGetSymbolAddress(&oh_ptr, g_oh);

    // 0. pack inputs to fp16
    k_packA<<<(M_ * HID_ / 2) / 256, 256>>>(x, (unsigned*)xh_ptr);
    k_packB<N3_><<<(HID_ / 2) * N3_ / 256, 256>>>(w_qkv, (unsigned*)wq_ptr);
    k_packB<HID_><<<(HID_ / 2) * HID_ / 256, 256>>>(w_o, (unsigned*)wo_ptr);

    // 1. QKV projection
    k_gemm_hp<N3_, 1><<<dim3(N3_ / 128, M_ / 128), 256>>>((const unsigned*)xh_ptr, (const unsigned*)wq_ptr, nullptr);
    // 2. RoPE; kerple table; V transpose
    k_rope2<<<(B_ * H_ * L_ * 32) / 256, 256>>>();
    k_ktab<<<4, 256>>>(log_p, log_a);
    k_vt<<<dim3(8, B_ * H_), 256>>>();
    // 3. scores
    k_scores_h<<<dim3(8, 8, B_ * H_), 256>>>();
    // 4. kerple + DAPE MLP (tanh gelu)
    k_dape3<<<dim3(4, L_, B_), 256>>>(w1, b1, w2, b2);
    // 5. softmax -> fp16 weights
    k_softmax<<<B_ * H_ * L_, 128>>>();
    // 6. PV (cp.async) -> packed fp16 g_oh
    k_pv_h<<<dim3(8, B_ * H_), 256>>>();
    // 7. output projection -> y fp32
    k_gemm_hp<HID_, 0><<<dim3(HID_ / 128, M_ / 128), 256>>>((const unsigned*)oh_ptr, (const unsigned*)wo_ptr, y);
}